// round 8
// baseline (speedup 1.0000x reference)
#include <cuda_runtime.h>
#include <cuda.h>
#include <cuda_bf16.h>
#include <math.h>
#include <cstdint>

// ---------------- problem constants ----------------
#define NT 10000      // total nodes
#define NE 120000     // edges
#define HCMAX 512

// per-layer weight-buffer offsets (elements) in g_Bh/g_Bl
#define WOFF0 0                 // layer0: 2*512*64  = 65536
#define WOFF1 65536             // layer1: 2*512*512 = 524288
#define WOFF2 589824            // layer2: 2*256*512 = 262144
#define WTOT  851968

// ---------------- device scratch ----------------
__device__ float g_XL[NT * HCMAX];
__device__ float g_XR[NT * HCMAX];
__device__ __nv_bfloat16 g_Ah[NT * HCMAX];
__device__ __nv_bfloat16 g_Al[NT * HCMAX];
__device__ __nv_bfloat16 g_Bh[WTOT];
__device__ __nv_bfloat16 g_Bl[WTOT];
__device__ int   g_deg[NT];
__device__ int   g_start[NT + 1];
__device__ int   g_cursor[NT];
__device__ int   g_csr[NE];

// ---------------- device helpers ----------------
__device__ __forceinline__ uint32_t smem_to_u32(const void* p) {
    uint32_t a;
    asm("{ .reg .u64 t; cvta.to.shared.u64 t, %1; cvt.u32.u64 %0, t; }" : "=r"(a) : "l"(p));
    return a;
}
__device__ __forceinline__ void ldsm_x4(uint32_t* r, uint32_t addr) {
    asm volatile("ldmatrix.sync.aligned.m8n8.x4.shared.b16 {%0,%1,%2,%3}, [%4];"
                 : "=r"(r[0]), "=r"(r[1]), "=r"(r[2]), "=r"(r[3]) : "r"(addr));
}
__device__ __forceinline__ void mma_bf16(float* c, const uint32_t* a, const uint32_t* b) {
    asm volatile("mma.sync.aligned.m16n8k16.row.col.f32.bf16.bf16.f32 "
                 "{%0,%1,%2,%3}, {%4,%5,%6,%7}, {%8,%9}, {%0,%1,%2,%3};"
                 : "+f"(c[0]), "+f"(c[1]), "+f"(c[2]), "+f"(c[3])
                 : "r"(a[0]), "r"(a[1]), "r"(a[2]), "r"(a[3]), "r"(b[0]), "r"(b[1]));
}
__device__ __forceinline__ void tma2d(uint32_t smem, const CUtensorMap* m, int x, int y, uint32_t mb) {
    asm volatile("cp.async.bulk.tensor.2d.shared::cta.global.tile.mbarrier::complete_tx::bytes "
                 "[%0], [%1, {%2, %3}], [%4];"
                 :: "r"(smem), "l"(m), "r"(x), "r"(y), "r"(mb) : "memory");
}
__device__ __forceinline__ void mbar_init(uint32_t mb, uint32_t cnt) {
    asm volatile("mbarrier.init.shared.b64 [%0], %1;" :: "r"(mb), "r"(cnt) : "memory");
}
__device__ __forceinline__ void mbar_expect(uint32_t mb, uint32_t bytes) {
    asm volatile("mbarrier.arrive.expect_tx.shared.b64 _, [%0], %1;" :: "r"(mb), "r"(bytes) : "memory");
}
__device__ __forceinline__ void mbar_wait(uint32_t mb, uint32_t par) {
    uint32_t done;
    asm volatile("{ .reg .pred p; mbarrier.try_wait.parity.acquire.cta.shared::cta.b64 p, [%1], %2;"
                 " selp.b32 %0, 1, 0, p; }" : "=r"(done) : "r"(mb), "r"(par) : "memory");
    if (!done) {
        asm volatile("{ .reg .pred P1; WL_%=: mbarrier.try_wait.parity.acquire.cta.shared::cta.b64 P1, [%0], %1, 0x989680;"
                     " @P1 bra.uni WD_%=; bra.uni WL_%=; WD_%=: }"
                     :: "r"(mb), "r"(par) : "memory");
    }
}
__device__ __forceinline__ uint32_t sw64(uint32_t o) { return o ^ ((o >> 3) & 0x30); }

// ---------------- CSR build ----------------
__global__ void k_zero_deg() {
    int i = blockIdx.x * blockDim.x + threadIdx.x;
    if (i < NT) g_deg[i] = 0;
}
__global__ void k_hist(const int* __restrict__ dst) {
    int e = blockIdx.x * blockDim.x + threadIdx.x;
    if (e < NE) atomicAdd(&g_deg[dst[e]], 1);
}
// 1024-thread single-block scan, 10 nodes per thread
__global__ void __launch_bounds__(1024) k_scan() {
    __shared__ int sh[1024];
    const int CH = (NT + 1023) / 1024;   // 10
    int tid = threadIdx.x;
    int base = tid * CH;
    int loc[10];
    int s = 0;
#pragma unroll
    for (int i = 0; i < 10; i++) {
        int n = base + i;
        int d = (i < CH && n < NT) ? g_deg[n] : 0;
        loc[i] = d;
        s += d;
    }
    sh[tid] = s;
    __syncthreads();
    for (int off = 1; off < 1024; off <<= 1) {
        int v = (tid >= off) ? sh[tid - off] : 0;
        __syncthreads();
        sh[tid] += v;
        __syncthreads();
    }
    int run = sh[tid] - s;   // exclusive prefix of this chunk
#pragma unroll
    for (int i = 0; i < 10; i++) {
        int n = base + i;
        if (i < CH && n < NT) {
            g_start[n]  = run;
            g_cursor[n] = run;
            run += loc[i];
        }
    }
    if (tid == 1023) g_start[NT] = sh[1023];
}
__global__ void k_scatter(const int* __restrict__ dst) {
    int e = blockIdx.x * blockDim.x + threadIdx.x;
    if (e < NE) {
        int p = atomicAdd(&g_cursor[dst[e]], 1);
        g_csr[p] = e;
    }
}

// ---------------- fp32 -> bf16 hi/lo split ----------------
__global__ void k_split(const float* __restrict__ in, __nv_bfloat16* __restrict__ hi,
                        __nv_bfloat16* __restrict__ lo, int n) {
    int i = blockIdx.x * blockDim.x + threadIdx.x;
    if (i < n) {
        float v = in[i];
        __nv_bfloat16 h = __float2bfloat16(v);
        hi[i] = h;
        lo[i] = __float2bfloat16(v - __bfloat162float(h));
    }
}
__global__ void k_splitW2(const float* __restrict__ W0, const float* __restrict__ W1,
                          __nv_bfloat16* __restrict__ hi, __nv_bfloat16* __restrict__ lo,
                          int K, int N) {
    const float* W = blockIdx.y ? W1 : W0;
    size_t off = (size_t)blockIdx.y * N * K;
    int i = blockIdx.x * blockDim.x + threadIdx.x;
    if (i < N * K) {
        int n = i / K, k = i - n * K;
        float v = W[(size_t)k * N + n];
        __nv_bfloat16 h = __float2bfloat16(v);
        hi[off + i] = h;
        lo[off + i] = __float2bfloat16(v - __bfloat162float(h));
    }
}

// ---------------- TMA-fed HMMA dual GEMM with bf16 error-split ----------------
constexpr int TILE_SZ  = 128 * 64;         // 8192 B
constexpr int STAGE_SZ = 4 * TILE_SZ;      // 32768 B
constexpr int NSTAGE   = 3;
constexpr int GEMM_DYN = NSTAGE * STAGE_SZ + 1024 + 64;

__global__ void __launch_bounds__(256, 2)
k_gemm_tma(const __grid_constant__ CUtensorMap tAh, const __grid_constant__ CUtensorMap tAl,
           const __grid_constant__ CUtensorMap tBh, const __grid_constant__ CUtensorMap tBl,
           const float* __restrict__ bias0, const float* __restrict__ bias1,
           float* __restrict__ C0, float* __restrict__ C1,
           int M, int N, int K) {
    extern __shared__ char smem[];
    const uint32_t sraw  = smem_to_u32(smem);
    const uint32_t sbase = (sraw + 1023u) & ~1023u;
    const uint32_t mbars = sbase + NSTAGE * STAGE_SZ;

    const int tid  = threadIdx.x;
    const int lane = tid & 31;
    const int wid  = tid >> 5;
    const int wm   = (wid & 3) * 32;
    const int wn   = (wid >> 2) * 64;
    const int row0 = blockIdx.y * 128;
    const int col0 = blockIdx.x * 128;
    const int brow = (int)blockIdx.z * N + col0;
    const float* bias = blockIdx.z ? bias1 : bias0;
    float*       C    = blockIdx.z ? C1 : C0;

    if (tid == 0) {
#pragma unroll
        for (int s = 0; s < NSTAGE; s++) mbar_init(mbars + s * 8, 1);
    }
    __syncthreads();

    const int nsteps = K / 32;

    auto issue = [&](int s) {
        if (tid == 0) {
            const int buf = s % NSTAGE;
            const uint32_t sb = sbase + buf * STAGE_SZ;
            const uint32_t mb = mbars + buf * 8;
            const int k0 = s * 32;
            mbar_expect(mb, STAGE_SZ);
            tma2d(sb,               &tAh, k0, row0, mb);
            tma2d(sb + TILE_SZ,     &tAl, k0, row0, mb);
            tma2d(sb + 2 * TILE_SZ, &tBh, k0, brow, mb);
            tma2d(sb + 3 * TILE_SZ, &tBl, k0, brow, mb);
        }
    };

    float acc[2][8][4];
#pragma unroll
    for (int mi = 0; mi < 2; mi++)
#pragma unroll
        for (int ni = 0; ni < 8; ni++)
#pragma unroll
            for (int j = 0; j < 4; j++) acc[mi][ni][j] = 0.f;

    issue(0);
    if (nsteps > 1) issue(1);

    int ph[NSTAGE] = {0, 0, 0};

    for (int s = 0; s < nsteps; s++) {
        const int buf = s % NSTAGE;
        mbar_wait(mbars + buf * 8, ph[buf]);
        ph[buf] ^= 1;

        const uint32_t uA  = sbase + buf * STAGE_SZ;
        const uint32_t uAl = uA + TILE_SZ;
        const uint32_t uB  = uA + 2 * TILE_SZ;
        const uint32_t uBl = uA + 3 * TILE_SZ;

#pragma unroll
        for (int ks = 0; ks < 2; ks++) {
            const int kcb = ks * 32;
            uint32_t fAh[2][4], fAl[2][4];
            {
                const int arow = wm + (lane & 15);
                const int acb  = kcb + (lane >> 4) * 16;
#pragma unroll
                for (int mi = 0; mi < 2; mi++) {
                    uint32_t lin = (uint32_t)((arow + mi * 16) * 64 + acb);
                    uint32_t ad  = sw64(lin);
                    ldsm_x4(fAh[mi], uA  + ad);
                    ldsm_x4(fAl[mi], uAl + ad);
                }
            }
            uint32_t fBh[4][4], fBl[4][4];
            {
                const int br = (lane & 7) + ((lane >> 4) & 1) * 8;
                const int bcb = kcb + ((lane >> 3) & 1) * 16;
#pragma unroll
                for (int g = 0; g < 4; g++) {
                    uint32_t lin = (uint32_t)((wn + g * 16 + br) * 64 + bcb);
                    uint32_t ad  = sw64(lin);
                    ldsm_x4(fBh[g], uB  + ad);
                    ldsm_x4(fBl[g], uBl + ad);
                }
            }
#pragma unroll
            for (int mi = 0; mi < 2; mi++)
#pragma unroll
                for (int ni = 0; ni < 8; ni++) {
                    const uint32_t* bh = &fBh[ni >> 1][(ni & 1) * 2];
                    const uint32_t* bl = &fBl[ni >> 1][(ni & 1) * 2];
                    mma_bf16(acc[mi][ni], fAh[mi], bh);
                    mma_bf16(acc[mi][ni], fAh[mi], bl);
                    mma_bf16(acc[mi][ni], fAl[mi], bh);
                }
        }
        __syncthreads();
        if (s + 2 < nsteps) issue(s + 2);
    }

    const int g  = lane >> 2;
    const int tg = lane & 3;
#pragma unroll
    for (int mi = 0; mi < 2; mi++) {
        int r0 = row0 + wm + mi * 16 + g;
        int r1 = r0 + 8;
#pragma unroll
        for (int ni = 0; ni < 8; ni++) {
            int cc = col0 + wn + ni * 8 + tg * 2;
            float b0 = bias[cc], b1 = bias[cc + 1];
            if (r0 < M) {
                float2 o = make_float2(acc[mi][ni][0] + b0, acc[mi][ni][1] + b1);
                *(float2*)&C[(size_t)r0 * N + cc] = o;
            }
            if (r1 < M) {
                float2 o = make_float2(acc[mi][ni][2] + b0, acc[mi][ni][3] + b1);
                *(float2*)&C[(size_t)r1 * N + cc] = o;
            }
        }
    }
}

// ---------------- warp-per-(node,head) GATv2 aggregation, online softmax ----------------
template <int H, int C, bool DO_ELU, bool SPLIT_OUT>
__global__ void __launch_bounds__(128)
k_gat_agg(const float* __restrict__ ew,
          const int*   __restrict__ srcArr,
          const float* __restrict__ We,
          const float* __restrict__ att,
          const float* __restrict__ bias,
          float* __restrict__ outF,
          __nv_bfloat16* __restrict__ outH,
          __nv_bfloat16* __restrict__ outL) {
    constexpr int HC  = H * C;
    constexpr int VPT = C / 32;

    const int wid  = threadIdx.x >> 5;
    const int lane = threadIdx.x & 31;

    int nd, h;
    if constexpr (H == 4) { nd = blockIdx.x; h = wid; }
    else                  { nd = blockIdx.x * 4 + wid; h = 0; if (nd >= NT) return; }
    const int chb = h * C + lane * VPT;

    float rxr[VPT], rWe[VPT], ratt[VPT];
#pragma unroll
    for (int j = 0; j < VPT; j += 4) {
        *(float4*)&rxr[j]  = *(const float4*)&g_XR[(size_t)nd * HC + chb + j];
        *(float4*)&rWe[j]  = *(const float4*)&We[chb + j];
        *(float4*)&ratt[j] = *(const float4*)&att[chb + j];
    }

    const int s0  = g_start[nd];
    const int deg = g_start[nd + 1] - s0;

    float m = -INFINITY, ssum = 0.f;
    float acc[VPT];
#pragma unroll
    for (int j = 0; j < VPT; j++) acc[j] = 0.f;

    int   sN = 0;
    float wN = 0.f;
    if (deg > 0) { int e = g_csr[s0]; sN = srcArr[e]; wN = ew[e]; }

    for (int eo = 0; eo < deg; eo++) {
        const int   s = sN;
        const float w = wN;
        if (eo + 1 < deg) { int e2 = g_csr[s0 + eo + 1]; sN = srcArr[e2]; wN = ew[e2]; }

        const float* xp = &g_XL[(size_t)s * HC + chb];
        float xv[VPT];
#pragma unroll
        for (int j = 0; j < VPT; j += 4)
            *(float4*)&xv[j] = *(const float4*)(xp + j);

        float partial = 0.f;
#pragma unroll
        for (int j = 0; j < VPT; j++) {
            float v = xv[j] + rxr[j] + w * rWe[j];
            v = (v > 0.f) ? v : 0.2f * v;
            partial += v * ratt[j];
        }
#pragma unroll
        for (int off = 16; off; off >>= 1)
            partial += __shfl_xor_sync(0xffffffff, partial, off);
        const float l = partial;

        const float mnew  = fmaxf(m, l);
        const float scale = __expf(m - mnew);
        const float p     = __expf(l - mnew);
        ssum = ssum * scale + p;
#pragma unroll
        for (int j = 0; j < VPT; j++)
            acc[j] = acc[j] * scale + p * xv[j];
        m = mnew;
    }

    const float inv = 1.f / (ssum + 1e-16f);
    const size_t ob = (size_t)nd * HC + chb;
#pragma unroll
    for (int j = 0; j < VPT; j++) {
        float o = acc[j] * inv + bias[chb + j];
        if constexpr (DO_ELU) o = (o > 0.f) ? o : expm1f(o);
        if constexpr (SPLIT_OUT) {
            __nv_bfloat16 hh = __float2bfloat16(o);
            outH[ob + j] = hh;
            outL[ob + j] = __float2bfloat16(o - __bfloat162float(hh));
        } else {
            outF[ob + j] = o;
        }
    }
}

// ---------------- host: tensor-map encode via runtime entry point ----------------
typedef CUresult (*EncodeFn)(CUtensorMap*, CUtensorMapDataType, cuuint32_t, void*,
                             const cuuint64_t*, const cuuint64_t*, const cuuint32_t*,
                             const cuuint32_t*, CUtensorMapInterleave, CUtensorMapSwizzle,
                             CUtensorMapL2promotion, CUtensorMapFloatOOBfill);

static EncodeFn get_encode_fn() {
    static EncodeFn fn = nullptr;
    if (!fn) {
        cudaDriverEntryPointQueryResult st;
        cudaGetDriverEntryPoint("cuTensorMapEncodeTiled", (void**)&fn, cudaEnableDefault, &st);
    }
    return fn;
}

static void make2d(CUtensorMap* m, void* ptr, int K, int rows) {
    cuuint64_t dims[2]    = {(cuuint64_t)K, (cuuint64_t)rows};
    cuuint64_t strides[1] = {(cuuint64_t)K * 2};
    cuuint32_t box[2]     = {32, 128};
    cuuint32_t es[2]      = {1, 1};
    get_encode_fn()(m, CU_TENSOR_MAP_DATA_TYPE_BFLOAT16, 2, ptr, dims, strides, box, es,
                    CU_TENSOR_MAP_INTERLEAVE_NONE, CU_TENSOR_MAP_SWIZZLE_64B,
                    CU_TENSOR_MAP_L2_PROMOTION_L2_128B, CU_TENSOR_MAP_FLOAT_OOB_FILL_NONE);
}

// ---------------- launch ----------------
extern "C" void kernel_launch(void* const* d_in, const int* in_sizes, int n_in,
                              void* d_out, int out_size) {
    const float* x   = (const float*)d_in[0];
    const int*   ei  = (const int*)  d_in[1];
    const float* ew  = (const float*)d_in[2];
    const int* src = ei;
    const int* dst = ei + NE;

    const float *Wl[3], *bl[3], *Wr[3], *br[3], *We[3], *att[3], *bias[3];
    for (int l = 0; l < 3; l++) {
        int b = 3 + 7 * l;
        Wl[l]   = (const float*)d_in[b + 0];
        bl[l]   = (const float*)d_in[b + 1];
        Wr[l]   = (const float*)d_in[b + 2];
        br[l]   = (const float*)d_in[b + 3];
        We[l]   = (const float*)d_in[b + 4];
        att[l]  = (const float*)d_in[b + 5];
        bias[l] = (const float*)d_in[b + 6];
    }

    float *dXL, *dXR;
    __nv_bfloat16 *dAh, *dAl, *dBh, *dBl;
    cudaGetSymbolAddress((void**)&dXL, g_XL);
    cudaGetSymbolAddress((void**)&dXR, g_XR);
    cudaGetSymbolAddress((void**)&dAh, g_Ah);
    cudaGetSymbolAddress((void**)&dAl, g_Al);
    cudaGetSymbolAddress((void**)&dBh, g_Bh);
    cudaGetSymbolAddress((void**)&dBl, g_Bl);
    float* dOut = (float*)d_out;

    cudaFuncSetAttribute(k_gemm_tma, cudaFuncAttributeMaxDynamicSharedMemorySize, GEMM_DYN);

    // one-time side stream + events
    static cudaStream_t sside = nullptr;
    static cudaEvent_t evFork = nullptr, evW0 = nullptr, evCsr = nullptr, evW12 = nullptr;
    if (!sside) {
        cudaStreamCreateWithFlags(&sside, cudaStreamNonBlocking);
        cudaEventCreateWithFlags(&evFork, cudaEventDisableTiming);
        cudaEventCreateWithFlags(&evW0,   cudaEventDisableTiming);
        cudaEventCreateWithFlags(&evCsr,  cudaEventDisableTiming);
        cudaEventCreateWithFlags(&evW12,  cudaEventDisableTiming);
    }

    // tensor maps
    CUtensorMap mA64h, mA64l, mA512h, mA512l;
    CUtensorMap mB0h, mB0l, mB1h, mB1l, mB2h, mB2l;
    make2d(&mA64h,  dAh, 64, NT);   make2d(&mA64l,  dAl, 64, NT);
    make2d(&mA512h, dAh, 512, NT);  make2d(&mA512l, dAl, 512, NT);
    make2d(&mB0h, dBh + WOFF0, 64,  2 * 512); make2d(&mB0l, dBl + WOFF0, 64,  2 * 512);
    make2d(&mB1h, dBh + WOFF1, 512, 2 * 512); make2d(&mB1l, dBl + WOFF1, 512, 2 * 512);
    make2d(&mB2h, dBh + WOFF2, 512, 2 * 256); make2d(&mB2l, dBl + WOFF2, 512, 2 * 256);

    const int MB = (NT + 127) / 128;   // 79

    // ---- enqueue order puts gemm0 at launch #6 for the ncu window ----
    k_split<<<(NT * 64 + 255) / 256, 256>>>(x, dAh, dAl, NT * 64);                        // 1 (main)

    cudaEventRecord(evFork, 0);
    cudaStreamWaitEvent(sside, evFork, 0);
    k_splitW2<<<dim3((512 * 64 + 255) / 256, 2), 256, 0, sside>>>(Wl[0], Wr[0],           // 2 (side)
                                                                  dBh + WOFF0, dBl + WOFF0, 64, 512);
    cudaEventRecord(evW0, sside);
    k_zero_deg<<<(NT + 255) / 256, 256, 0, sside>>>();                                    // 3 (side)
    k_hist    <<<(NE + 255) / 256, 256, 0, sside>>>(dst);                                 // 4 (side)
    k_scan    <<<1, 1024, 0, sside>>>();                                                  // 5 (side)

    // ---------- layer 0 GEMM ----------
    cudaStreamWaitEvent(0, evW0, 0);
    k_gemm_tma<<<dim3(512 / 128, MB, 2), 256, GEMM_DYN>>>(mA64h, mA64l, mB0h, mB0l,       // 6 (main)
                                                          bl[0], br[0], dXL, dXR, NT, 512, 64);

    k_scatter<<<(NE + 255) / 256, 256, 0, sside>>>(dst);                                  // 7 (side)
    cudaEventRecord(evCsr, sside);
    k_splitW2<<<dim3((512 * 512 + 255) / 256, 2), 256, 0, sside>>>(Wl[1], Wr[1],          // 8 (side)
                                                                   dBh + WOFF1, dBl + WOFF1, 512, 512);
    k_splitW2<<<dim3((256 * 512 + 255) / 256, 2), 256, 0, sside>>>(Wl[2], Wr[2],          // 9 (side)
                                                                   dBh + WOFF2, dBl + WOFF2, 512, 256);
    cudaEventRecord(evW12, sside);

    // ---------- layer 0 aggregate (needs CSR only) ----------
    cudaStreamWaitEvent(0, evCsr, 0);
    k_gat_agg<4, 128, true, true><<<NT, 128>>>(ew, src, We[0], att[0], bias[0],           // 10 (main)
                                               nullptr, dAh, dAl);

    // ---------- layer 1 ----------
    cudaStreamWaitEvent(0, evW12, 0);
    k_gemm_tma<<<dim3(512 / 128, MB, 2), 256, GEMM_DYN>>>(mA512h, mA512l, mB1h, mB1l,
                                                          bl[1], br[1], dXL, dXR, NT, 512, 512);
    k_gat_agg<4, 128, true, true><<<NT, 128>>>(ew, src, We[1], att[1], bias[1],
                                               nullptr, dAh, dAl);

    // ---------- layer 2 ----------
    k_gemm_tma<<<dim3(256 / 128, MB, 2), 256, GEMM_DYN>>>(mA512h, mA512l, mB2h, mB2l,
                                                          bl[2], br[2], dXL, dXR, NT, 256, 512);
    k_gat_agg<1, 256, false, false><<<(NT + 3) / 4, 128>>>(ew, src, We[2], att[2], bias[2],
                                                           dOut, nullptr, nullptr);
}

// round 9
// speedup vs baseline: 1.0145x; 1.0145x over previous
#include <cuda_runtime.h>
#include <cuda.h>
#include <cuda_bf16.h>
#include <math.h>
#include <cstdint>

// ---------------- problem constants ----------------
#define NT 10000      // total nodes
#define NE 120000     // edges
#define HCMAX 512

// per-layer weight-buffer offsets (elements) in g_Bh/g_Bl
#define WOFF0 0                 // layer0: 2*512*64  = 65536
#define WOFF1 65536             // layer1: 2*512*512 = 524288
#define WOFF2 589824            // layer2: 2*256*512 = 262144
#define WTOT  851968

// ---------------- device scratch ----------------
__device__ float g_XL[NT * HCMAX];
__device__ float g_XR[NT * HCMAX];
__device__ __nv_bfloat16 g_Ah[NT * HCMAX];
__device__ __nv_bfloat16 g_Al[NT * HCMAX];
__device__ __nv_bfloat16 g_Bh[WTOT];
__device__ __nv_bfloat16 g_Bl[WTOT];
__device__ int   g_deg[NT];
__device__ int   g_start[NT + 1];
__device__ int   g_cursor[NT];
__device__ int   g_csr[NE];

// ---------------- device helpers ----------------
__device__ __forceinline__ uint32_t smem_to_u32(const void* p) {
    uint32_t a;
    asm("{ .reg .u64 t; cvta.to.shared.u64 t, %1; cvt.u32.u64 %0, t; }" : "=r"(a) : "l"(p));
    return a;
}
__device__ __forceinline__ void ldsm_x4(uint32_t* r, uint32_t addr) {
    asm volatile("ldmatrix.sync.aligned.m8n8.x4.shared.b16 {%0,%1,%2,%3}, [%4];"
                 : "=r"(r[0]), "=r"(r[1]), "=r"(r[2]), "=r"(r[3]) : "r"(addr));
}
__device__ __forceinline__ void mma_bf16(float* c, const uint32_t* a, const uint32_t* b) {
    asm volatile("mma.sync.aligned.m16n8k16.row.col.f32.bf16.bf16.f32 "
                 "{%0,%1,%2,%3}, {%4,%5,%6,%7}, {%8,%9}, {%0,%1,%2,%3};"
                 : "+f"(c[0]), "+f"(c[1]), "+f"(c[2]), "+f"(c[3])
                 : "r"(a[0]), "r"(a[1]), "r"(a[2]), "r"(a[3]), "r"(b[0]), "r"(b[1]));
}
__device__ __forceinline__ void tma2d(uint32_t smem, const CUtensorMap* m, int x, int y, uint32_t mb) {
    asm volatile("cp.async.bulk.tensor.2d.shared::cta.global.tile.mbarrier::complete_tx::bytes "
                 "[%0], [%1, {%2, %3}], [%4];"
                 :: "r"(smem), "l"(m), "r"(x), "r"(y), "r"(mb) : "memory");
}
__device__ __forceinline__ void mbar_init(uint32_t mb, uint32_t cnt) {
    asm volatile("mbarrier.init.shared.b64 [%0], %1;" :: "r"(mb), "r"(cnt) : "memory");
}
__device__ __forceinline__ void mbar_expect(uint32_t mb, uint32_t bytes) {
    asm volatile("mbarrier.arrive.expect_tx.shared.b64 _, [%0], %1;" :: "r"(mb), "r"(bytes) : "memory");
}
__device__ __forceinline__ void mbar_wait(uint32_t mb, uint32_t par) {
    uint32_t done;
    asm volatile("{ .reg .pred p; mbarrier.try_wait.parity.acquire.cta.shared::cta.b64 p, [%1], %2;"
                 " selp.b32 %0, 1, 0, p; }" : "=r"(done) : "r"(mb), "r"(par) : "memory");
    if (!done) {
        asm volatile("{ .reg .pred P1; WL_%=: mbarrier.try_wait.parity.acquire.cta.shared::cta.b64 P1, [%0], %1, 0x989680;"
                     " @P1 bra.uni WD_%=; bra.uni WL_%=; WD_%=: }"
                     :: "r"(mb), "r"(par) : "memory");
    }
}
__device__ __forceinline__ uint32_t sw64(uint32_t o) { return o ^ ((o >> 3) & 0x30); }

// ---------------- CSR build ----------------
__global__ void k_hist(const int* __restrict__ dst) {
    int e = blockIdx.x * blockDim.x + threadIdx.x;
    if (e < NE) atomicAdd(&g_deg[dst[e]], 1);
}
// 1024-thread single-block scan, 10 nodes per thread
__global__ void __launch_bounds__(1024) k_scan() {
    __shared__ int sh[1024];
    const int CH = (NT + 1023) / 1024;   // 10
    int tid = threadIdx.x;
    int base = tid * CH;
    int loc[10];
    int s = 0;
#pragma unroll
    for (int i = 0; i < 10; i++) {
        int n = base + i;
        int d = (i < CH && n < NT) ? g_deg[n] : 0;
        loc[i] = d;
        s += d;
    }
    sh[tid] = s;
    __syncthreads();
    for (int off = 1; off < 1024; off <<= 1) {
        int v = (tid >= off) ? sh[tid - off] : 0;
        __syncthreads();
        sh[tid] += v;
        __syncthreads();
    }
    int run = sh[tid] - s;
#pragma unroll
    for (int i = 0; i < 10; i++) {
        int n = base + i;
        if (i < CH && n < NT) {
            g_start[n]  = run;
            g_cursor[n] = run;
            run += loc[i];
        }
    }
    if (tid == 1023) g_start[NT] = sh[1023];
}
__global__ void k_scatter(const int* __restrict__ dst) {
    int e = blockIdx.x * blockDim.x + threadIdx.x;
    if (e < NE) {
        int p = atomicAdd(&g_cursor[dst[e]], 1);
        g_csr[p] = e;
    }
}

// ---------------- fp32 -> bf16 hi/lo split ----------------
__global__ void k_split(const float* __restrict__ in, __nv_bfloat16* __restrict__ hi,
                        __nv_bfloat16* __restrict__ lo, int n) {
    int i = blockIdx.x * blockDim.x + threadIdx.x;
    if (i < n) {
        float v = in[i];
        __nv_bfloat16 h = __float2bfloat16(v);
        hi[i] = h;
        lo[i] = __float2bfloat16(v - __bfloat162float(h));
    }
}
__global__ void k_splitW2(const float* __restrict__ W0, const float* __restrict__ W1,
                          __nv_bfloat16* __restrict__ hi, __nv_bfloat16* __restrict__ lo,
                          int K, int N) {
    const float* W = blockIdx.y ? W1 : W0;
    size_t off = (size_t)blockIdx.y * N * K;
    int i = blockIdx.x * blockDim.x + threadIdx.x;
    if (i < N * K) {
        int n = i / K, k = i - n * K;
        float v = W[(size_t)k * N + n];
        __nv_bfloat16 h = __float2bfloat16(v);
        hi[off + i] = h;
        lo[off + i] = __float2bfloat16(v - __bfloat162float(h));
    }
}

// ---------------- TMA-fed HMMA dual GEMM with bf16 error-split ----------------
// B-fragments streamed in 16-col groups to keep live registers < 124 (no spills).
constexpr int TILE_SZ  = 128 * 64;         // 8192 B
constexpr int STAGE_SZ = 4 * TILE_SZ;      // 32768 B
constexpr int NSTAGE   = 3;
constexpr int GEMM_DYN = NSTAGE * STAGE_SZ + 1024 + 64;

__global__ void __launch_bounds__(256, 2)
k_gemm_tma(const __grid_constant__ CUtensorMap tAh, const __grid_constant__ CUtensorMap tAl,
           const __grid_constant__ CUtensorMap tBh, const __grid_constant__ CUtensorMap tBl,
           const float* __restrict__ bias0, const float* __restrict__ bias1,
           float* __restrict__ C0, float* __restrict__ C1,
           int M, int N, int K) {
    extern __shared__ char smem[];
    const uint32_t sraw  = smem_to_u32(smem);
    const uint32_t sbase = (sraw + 1023u) & ~1023u;
    const uint32_t mbars = sbase + NSTAGE * STAGE_SZ;

    const int tid  = threadIdx.x;
    const int lane = tid & 31;
    const int wid  = tid >> 5;
    const int wm   = (wid & 3) * 32;
    const int wn   = (wid >> 2) * 64;
    const int row0 = blockIdx.y * 128;
    const int col0 = blockIdx.x * 128;
    const int brow = (int)blockIdx.z * N + col0;
    const float* bias = blockIdx.z ? bias1 : bias0;
    float*       C    = blockIdx.z ? C1 : C0;

    if (tid == 0) {
#pragma unroll
        for (int s = 0; s < NSTAGE; s++) mbar_init(mbars + s * 8, 1);
    }
    __syncthreads();

    const int nsteps = K / 32;

    auto issue = [&](int s) {
        if (tid == 0) {
            const int buf = s % NSTAGE;
            const uint32_t sb = sbase + buf * STAGE_SZ;
            const uint32_t mb = mbars + buf * 8;
            const int k0 = s * 32;
            mbar_expect(mb, STAGE_SZ);
            tma2d(sb,               &tAh, k0, row0, mb);
            tma2d(sb + TILE_SZ,     &tAl, k0, row0, mb);
            tma2d(sb + 2 * TILE_SZ, &tBh, k0, brow, mb);
            tma2d(sb + 3 * TILE_SZ, &tBl, k0, brow, mb);
        }
    };

    float acc[2][8][4];
#pragma unroll
    for (int mi = 0; mi < 2; mi++)
#pragma unroll
        for (int ni = 0; ni < 8; ni++)
#pragma unroll
            for (int j = 0; j < 4; j++) acc[mi][ni][j] = 0.f;

    issue(0);
    if (nsteps > 1) issue(1);

    int ph[NSTAGE] = {0, 0, 0};

    for (int s = 0; s < nsteps; s++) {
        const int buf = s % NSTAGE;
        mbar_wait(mbars + buf * 8, ph[buf]);
        ph[buf] ^= 1;

        const uint32_t uA  = sbase + buf * STAGE_SZ;
        const uint32_t uAl = uA + TILE_SZ;
        const uint32_t uB  = uA + 2 * TILE_SZ;
        const uint32_t uBl = uA + 3 * TILE_SZ;

#pragma unroll
        for (int ks = 0; ks < 2; ks++) {
            const int kcb = ks * 32;
            uint32_t fAh[2][4], fAl[2][4];
            {
                const int arow = wm + (lane & 15);
                const int acb  = kcb + (lane >> 4) * 16;
#pragma unroll
                for (int mi = 0; mi < 2; mi++) {
                    uint32_t lin = (uint32_t)((arow + mi * 16) * 64 + acb);
                    uint32_t ad  = sw64(lin);
                    ldsm_x4(fAh[mi], uA  + ad);
                    ldsm_x4(fAl[mi], uAl + ad);
                }
            }
            // stream B in 16-col groups: only 8 B-frag regs live at a time
            const int br  = (lane & 7) + ((lane >> 4) & 1) * 8;
            const int bcb = kcb + ((lane >> 3) & 1) * 16;
#pragma unroll
            for (int g = 0; g < 4; g++) {
                uint32_t fBh[4], fBl[4];
                uint32_t lin = (uint32_t)((wn + g * 16 + br) * 64 + bcb);
                uint32_t ad  = sw64(lin);
                ldsm_x4(fBh, uB  + ad);
                ldsm_x4(fBl, uBl + ad);
#pragma unroll
                for (int mi = 0; mi < 2; mi++)
#pragma unroll
                    for (int nn = 0; nn < 2; nn++) {
                        const int ni = g * 2 + nn;
                        const uint32_t* bh = &fBh[nn * 2];
                        const uint32_t* bl = &fBl[nn * 2];
                        mma_bf16(acc[mi][ni], fAh[mi], bh);
                        mma_bf16(acc[mi][ni], fAh[mi], bl);
                        mma_bf16(acc[mi][ni], fAl[mi], bh);
                    }
            }
        }
        __syncthreads();
        if (s + 2 < nsteps) issue(s + 2);
    }

    const int g  = lane >> 2;
    const int tg = lane & 3;
#pragma unroll
    for (int mi = 0; mi < 2; mi++) {
        int r0 = row0 + wm + mi * 16 + g;
        int r1 = r0 + 8;
#pragma unroll
        for (int ni = 0; ni < 8; ni++) {
            int cc = col0 + wn + ni * 8 + tg * 2;
            float b0 = bias[cc], b1 = bias[cc + 1];
            if (r0 < M) {
                float2 o = make_float2(acc[mi][ni][0] + b0, acc[mi][ni][1] + b1);
                *(float2*)&C[(size_t)r0 * N + cc] = o;
            }
            if (r1 < M) {
                float2 o = make_float2(acc[mi][ni][2] + b0, acc[mi][ni][3] + b1);
                *(float2*)&C[(size_t)r1 * N + cc] = o;
            }
        }
    }
}

// ---------------- warp-per-(node,head) GATv2 aggregation ----------------
// Online softmax; indices prefetched 2 edges ahead, xl-row data 1 edge ahead.
template <int H, int C, bool DO_ELU, bool SPLIT_OUT>
__global__ void __launch_bounds__(128)
k_gat_agg(const float* __restrict__ ew,
          const int*   __restrict__ srcArr,
          const float* __restrict__ We,
          const float* __restrict__ att,
          const float* __restrict__ bias,
          float* __restrict__ outF,
          __nv_bfloat16* __restrict__ outH,
          __nv_bfloat16* __restrict__ outL) {
    constexpr int HC  = H * C;
    constexpr int VPT = C / 32;

    const int wid  = threadIdx.x >> 5;
    const int lane = threadIdx.x & 31;

    int nd, h;
    if constexpr (H == 4) { nd = blockIdx.x; h = wid; }
    else                  { nd = blockIdx.x * 4 + wid; h = 0; if (nd >= NT) return; }
    const int chb = h * C + lane * VPT;

    float rxr[VPT], rWe[VPT], ratt[VPT];
#pragma unroll
    for (int j = 0; j < VPT; j += 4) {
        *(float4*)&rxr[j]  = *(const float4*)&g_XR[(size_t)nd * HC + chb + j];
        *(float4*)&rWe[j]  = *(const float4*)&We[chb + j];
        *(float4*)&ratt[j] = *(const float4*)&att[chb + j];
    }

    const int s0  = g_start[nd];
    const int deg = g_start[nd + 1] - s0;

    float m = -INFINITY, ssum = 0.f;
    float acc[VPT];
#pragma unroll
    for (int j = 0; j < VPT; j++) acc[j] = 0.f;

    // pipeline state: idx queue depth 2, data depth 1
    int   sQ0 = 0, sQ1 = 0;
    float wQ0 = 0.f, wQ1 = 0.f;
    float xvC[VPT];
    if (deg > 0) { int e = g_csr[s0];     sQ0 = srcArr[e]; wQ0 = ew[e]; }
    if (deg > 1) { int e = g_csr[s0 + 1]; sQ1 = srcArr[e]; wQ1 = ew[e]; }
    if (deg > 0) {
        const float* xp = &g_XL[(size_t)sQ0 * HC + chb];
#pragma unroll
        for (int j = 0; j < VPT; j += 4) *(float4*)&xvC[j] = *(const float4*)(xp + j);
    }

    for (int eo = 0; eo < deg; eo++) {
        // prefetch indices for eo+2
        int sNN = 0; float wNN = 0.f;
        if (eo + 2 < deg) { int e = g_csr[s0 + eo + 2]; sNN = srcArr[e]; wNN = ew[e]; }
        // prefetch data for eo+1
        float xvN[VPT];
        if (eo + 1 < deg) {
            const float* xp = &g_XL[(size_t)sQ1 * HC + chb];
#pragma unroll
            for (int j = 0; j < VPT; j += 4) *(float4*)&xvN[j] = *(const float4*)(xp + j);
        }

        // compute with current edge
        const float w = wQ0;
        float partial = 0.f;
#pragma unroll
        for (int j = 0; j < VPT; j++) {
            float v = xvC[j] + rxr[j] + w * rWe[j];
            v = (v > 0.f) ? v : 0.2f * v;
            partial += v * ratt[j];
        }
#pragma unroll
        for (int off = 16; off; off >>= 1)
            partial += __shfl_xor_sync(0xffffffff, partial, off);
        const float l = partial;

        const float mnew  = fmaxf(m, l);
        const float scale = __expf(m - mnew);
        const float p     = __expf(l - mnew);
        ssum = ssum * scale + p;
#pragma unroll
        for (int j = 0; j < VPT; j++)
            acc[j] = acc[j] * scale + p * xvC[j];
        m = mnew;

        // rotate pipeline
#pragma unroll
        for (int j = 0; j < VPT; j++) xvC[j] = xvN[j];
        sQ0 = sQ1; wQ0 = wQ1;
        sQ1 = sNN; wQ1 = wNN;
    }

    const float inv = 1.f / (ssum + 1e-16f);
    const size_t ob = (size_t)nd * HC + chb;
#pragma unroll
    for (int j = 0; j < VPT; j++) {
        float o = acc[j] * inv + bias[chb + j];
        if constexpr (DO_ELU) o = (o > 0.f) ? o : expm1f(o);
        if constexpr (SPLIT_OUT) {
            __nv_bfloat16 hh = __float2bfloat16(o);
            outH[ob + j] = hh;
            outL[ob + j] = __float2bfloat16(o - __bfloat162float(hh));
        } else {
            outF[ob + j] = o;
        }
    }
}

// ---------------- host: tensor-map encode via runtime entry point ----------------
typedef CUresult (*EncodeFn)(CUtensorMap*, CUtensorMapDataType, cuuint32_t, void*,
                             const cuuint64_t*, const cuuint64_t*, const cuuint32_t*,
                             const cuuint32_t*, CUtensorMapInterleave, CUtensorMapSwizzle,
                             CUtensorMapL2promotion, CUtensorMapFloatOOBfill);

static EncodeFn get_encode_fn() {
    static EncodeFn fn = nullptr;
    if (!fn) {
        cudaDriverEntryPointQueryResult st;
        cudaGetDriverEntryPoint("cuTensorMapEncodeTiled", (void**)&fn, cudaEnableDefault, &st);
    }
    return fn;
}

static void make2d(CUtensorMap* m, void* ptr, int K, int rows) {
    cuuint64_t dims[2]    = {(cuuint64_t)K, (cuuint64_t)rows};
    cuuint64_t strides[1] = {(cuuint64_t)K * 2};
    cuuint32_t box[2]     = {32, 128};
    cuuint32_t es[2]      = {1, 1};
    get_encode_fn()(m, CU_TENSOR_MAP_DATA_TYPE_BFLOAT16, 2, ptr, dims, strides, box, es,
                    CU_TENSOR_MAP_INTERLEAVE_NONE, CU_TENSOR_MAP_SWIZZLE_64B,
                    CU_TENSOR_MAP_L2_PROMOTION_L2_128B, CU_TENSOR_MAP_FLOAT_OOB_FILL_NONE);
}

// ---------------- launch ----------------
extern "C" void kernel_launch(void* const* d_in, const int* in_sizes, int n_in,
                              void* d_out, int out_size) {
    const float* x   = (const float*)d_in[0];
    const int*   ei  = (const int*)  d_in[1];
    const float* ew  = (const float*)d_in[2];
    const int* src = ei;
    const int* dst = ei + NE;

    const float *Wl[3], *bl[3], *Wr[3], *br[3], *We[3], *att[3], *bias[3];
    for (int l = 0; l < 3; l++) {
        int b = 3 + 7 * l;
        Wl[l]   = (const float*)d_in[b + 0];
        bl[l]   = (const float*)d_in[b + 1];
        Wr[l]   = (const float*)d_in[b + 2];
        br[l]   = (const float*)d_in[b + 3];
        We[l]   = (const float*)d_in[b + 4];
        att[l]  = (const float*)d_in[b + 5];
        bias[l] = (const float*)d_in[b + 6];
    }

    float *dXL, *dXR;
    __nv_bfloat16 *dAh, *dAl, *dBh, *dBl;
    int *dDeg;
    cudaGetSymbolAddress((void**)&dXL, g_XL);
    cudaGetSymbolAddress((void**)&dXR, g_XR);
    cudaGetSymbolAddress((void**)&dAh, g_Ah);
    cudaGetSymbolAddress((void**)&dAl, g_Al);
    cudaGetSymbolAddress((void**)&dBh, g_Bh);
    cudaGetSymbolAddress((void**)&dBl, g_Bl);
    cudaGetSymbolAddress((void**)&dDeg, g_deg);
    float* dOut = (float*)d_out;

    cudaFuncSetAttribute(k_gemm_tma, cudaFuncAttributeMaxDynamicSharedMemorySize, GEMM_DYN);

    // one-time side stream + events
    static cudaStream_t sside = nullptr;
    static cudaEvent_t evFork = nullptr, evW0 = nullptr, evCsr = nullptr, evW12 = nullptr;
    if (!sside) {
        cudaStreamCreateWithFlags(&sside, cudaStreamNonBlocking);
        cudaEventCreateWithFlags(&evFork, cudaEventDisableTiming);
        cudaEventCreateWithFlags(&evW0,   cudaEventDisableTiming);
        cudaEventCreateWithFlags(&evCsr,  cudaEventDisableTiming);
        cudaEventCreateWithFlags(&evW12,  cudaEventDisableTiming);
    }

    // tensor maps
    CUtensorMap mA64h, mA64l, mA512h, mA512l;
    CUtensorMap mB0h, mB0l, mB1h, mB1l, mB2h, mB2l;
    make2d(&mA64h,  dAh, 64, NT);   make2d(&mA64l,  dAl, 64, NT);
    make2d(&mA512h, dAh, 512, NT);  make2d(&mA512l, dAl, 512, NT);
    make2d(&mB0h, dBh + WOFF0, 64,  2 * 512); make2d(&mB0l, dBl + WOFF0, 64,  2 * 512);
    make2d(&mB1h, dBh + WOFF1, 512, 2 * 512); make2d(&mB1l, dBl + WOFF1, 512, 2 * 512);
    make2d(&mB2h, dBh + WOFF2, 512, 2 * 256); make2d(&mB2l, dBl + WOFF2, 512, 2 * 256);

    const int MB = (NT + 127) / 128;   // 79

    // ---- fork side stream immediately (before any main kernel) ----
    cudaEventRecord(evFork, 0);
    cudaStreamWaitEvent(sside, evFork, 0);

    // submission #1 (main)
    k_split<<<(NT * 64 + 255) / 256, 256>>>(x, dAh, dAl, NT * 64);

    // side: layer-0 weights, then CSR build (zero_deg via memset, not a kernel)
    k_splitW2<<<dim3((512 * 64 + 255) / 256, 2), 256, 0, sside>>>(Wl[0], Wr[0],        // #2
                                                                  dBh + WOFF0, dBl + WOFF0, 64, 512);
    cudaEventRecord(evW0, sside);
    cudaMemsetAsync(dDeg, 0, NT * sizeof(int), sside);
    k_hist<<<(NE + 255) / 256, 256, 0, sside>>>(dst);                                  // #3

    // ---------- layer 0 GEMM (submission #4) ----------
    cudaStreamWaitEvent(0, evW0, 0);
    k_gemm_tma<<<dim3(512 / 128, MB, 2), 256, GEMM_DYN>>>(mA64h, mA64l, mB0h, mB0l,
                                                          bl[0], br[0], dXL, dXR, NT, 512, 64);

    k_scan   <<<1, 1024, 0, sside>>>();                                                // #5
    k_scatter<<<(NE + 255) / 256, 256, 0, sside>>>(dst);                               // #6
    cudaEventRecord(evCsr, sside);
    k_splitW2<<<dim3((512 * 512 + 255) / 256, 2), 256, 0, sside>>>(Wl[1], Wr[1],       // #7
                                                                   dBh + WOFF1, dBl + WOFF1, 512, 512);
    k_splitW2<<<dim3((256 * 512 + 255) / 256, 2), 256, 0, sside>>>(Wl[2], Wr[2],       // #8
                                                                   dBh + WOFF2, dBl + WOFF2, 512, 256);
    cudaEventRecord(evW12, sside);

    // ---------- layer 0 aggregate ----------
    cudaStreamWaitEvent(0, evCsr, 0);
    k_gat_agg<4, 128, true, true><<<NT, 128>>>(ew, src, We[0], att[0], bias[0],
                                               nullptr, dAh, dAl);

    // ---------- layer 1 ----------
    cudaStreamWaitEvent(0, evW12, 0);
    k_gemm_tma<<<dim3(512 / 128, MB, 2), 256, GEMM_DYN>>>(mA512h, mA512l, mB1h, mB1l,
                                                          bl[1], br[1], dXL, dXR, NT, 512, 512);
    k_gat_agg<4, 128, true, true><<<NT, 128>>>(ew, src, We[1], att[1], bias[1],
                                               nullptr, dAh, dAl);

    // ---------- layer 2 ----------
    k_gemm_tma<<<dim3(256 / 128, MB, 2), 256, GEMM_DYN>>>(mA512h, mA512l, mB2h, mB2l,
                                                          bl[2], br[2], dXL, dXR, NT, 256, 512);
    k_gat_agg<1, 256, false, false><<<(NT + 3) / 4, 128>>>(ew, src, We[2], att[2], bias[2],
                                                           dOut, nullptr, nullptr);
}

// round 12
// speedup vs baseline: 1.0208x; 1.0062x over previous
#include <cuda_runtime.h>
#include <cuda.h>
#include <cuda_bf16.h>
#include <math.h>
#include <cstdint>

// ---------------- problem constants ----------------
#define NT 10000      // total nodes
#define NE 120000     // edges
#define HCMAX 512

// per-layer weight-buffer offsets (elements) in g_Bh/g_Bl
#define WOFF0 0                 // layer0: 2*512*64  = 65536
#define WOFF1 65536             // layer1: 2*512*512 = 524288
#define WOFF2 589824            // layer2: 2*256*512 = 262144
#define WTOT  851968

// ---------------- device scratch ----------------
__device__ float g_XL[NT * HCMAX];
__device__ float g_XR[NT * HCMAX];
__device__ __nv_bfloat16 g_Ah[NT * HCMAX];
__device__ __nv_bfloat16 g_Al[NT * HCMAX];
__device__ __nv_bfloat16 g_Bh[WTOT];
__device__ __nv_bfloat16 g_Bl[WTOT];
__device__ int   g_deg[NT];
__device__ int   g_start[NT + 1];
__device__ int   g_cursor[NT];
__device__ int   g_csr[NE];

// ---------------- device helpers ----------------
__device__ __forceinline__ uint32_t smem_to_u32(const void* p) {
    uint32_t a;
    asm("{ .reg .u64 t; cvta.to.shared.u64 t, %1; cvt.u32.u64 %0, t; }" : "=r"(a) : "l"(p));
    return a;
}
__device__ __forceinline__ void ldsm_x4(uint32_t* r, uint32_t addr) {
    asm volatile("ldmatrix.sync.aligned.m8n8.x4.shared.b16 {%0,%1,%2,%3}, [%4];"
                 : "=r"(r[0]), "=r"(r[1]), "=r"(r[2]), "=r"(r[3]) : "r"(addr));
}
__device__ __forceinline__ void mma_bf16(float* c, const uint32_t* a, const uint32_t* b) {
    asm volatile("mma.sync.aligned.m16n8k16.row.col.f32.bf16.bf16.f32 "
                 "{%0,%1,%2,%3}, {%4,%5,%6,%7}, {%8,%9}, {%0,%1,%2,%3};"
                 : "+f"(c[0]), "+f"(c[1]), "+f"(c[2]), "+f"(c[3])
                 : "r"(a[0]), "r"(a[1]), "r"(a[2]), "r"(a[3]), "r"(b[0]), "r"(b[1]));
}
__device__ __forceinline__ void tma2d(uint32_t smem, const CUtensorMap* m, int x, int y, uint32_t mb) {
    asm volatile("cp.async.bulk.tensor.2d.shared::cta.global.tile.mbarrier::complete_tx::bytes "
                 "[%0], [%1, {%2, %3}], [%4];"
                 :: "r"(smem), "l"(m), "r"(x), "r"(y), "r"(mb) : "memory");
}
__device__ __forceinline__ void mbar_init(uint32_t mb, uint32_t cnt) {
    asm volatile("mbarrier.init.shared.b64 [%0], %1;" :: "r"(mb), "r"(cnt) : "memory");
}
__device__ __forceinline__ void mbar_expect(uint32_t mb, uint32_t bytes) {
    asm volatile("mbarrier.arrive.expect_tx.shared.b64 _, [%0], %1;" :: "r"(mb), "r"(bytes) : "memory");
}
__device__ __forceinline__ void mbar_wait(uint32_t mb, uint32_t par) {
    uint32_t done;
    asm volatile("{ .reg .pred p; mbarrier.try_wait.parity.acquire.cta.shared::cta.b64 p, [%1], %2;"
                 " selp.b32 %0, 1, 0, p; }" : "=r"(done) : "r"(mb), "r"(par) : "memory");
    if (!done) {
        asm volatile("{ .reg .pred P1; WL_%=: mbarrier.try_wait.parity.acquire.cta.shared::cta.b64 P1, [%0], %1, 0x989680;"
                     " @P1 bra.uni WD_%=; bra.uni WL_%=; WD_%=: }"
                     :: "r"(mb), "r"(par) : "memory");
    }
}
__device__ __forceinline__ uint32_t sw64(uint32_t o) { return o ^ ((o >> 3) & 0x30); }

// ---------------- CSR build ----------------
__global__ void k_hist(const int* __restrict__ dst) {
    int e = blockIdx.x * blockDim.x + threadIdx.x;
    if (e < NE) atomicAdd(&g_deg[dst[e]], 1);
}
__global__ void __launch_bounds__(1024) k_scan() {
    __shared__ int sh[1024];
    const int CH = (NT + 1023) / 1024;   // 10
    int tid = threadIdx.x;
    int base = tid * CH;
    int loc[10];
    int s = 0;
#pragma unroll
    for (int i = 0; i < 10; i++) {
        int n = base + i;
        int d = (i < CH && n < NT) ? g_deg[n] : 0;
        loc[i] = d;
        s += d;
    }
    sh[tid] = s;
    __syncthreads();
    for (int off = 1; off < 1024; off <<= 1) {
        int v = (tid >= off) ? sh[tid - off] : 0;
        __syncthreads();
        sh[tid] += v;
        __syncthreads();
    }
    int run = sh[tid] - s;
#pragma unroll
    for (int i = 0; i < 10; i++) {
        int n = base + i;
        if (i < CH && n < NT) {
            g_start[n]  = run;
            g_cursor[n] = run;
            run += loc[i];
        }
    }
    if (tid == 1023) g_start[NT] = sh[1023];
}
__global__ void k_scatter(const int* __restrict__ dst) {
    int e = blockIdx.x * blockDim.x + threadIdx.x;
    if (e < NE) {
        int p = atomicAdd(&g_cursor[dst[e]], 1);
        g_csr[p] = e;
    }
}

// ---------------- fp32 -> bf16 hi/lo split ----------------
__global__ void k_split(const float* __restrict__ in, __nv_bfloat16* __restrict__ hi,
                        __nv_bfloat16* __restrict__ lo, int n) {
    int i = blockIdx.x * blockDim.x + threadIdx.x;
    if (i < n) {
        float v = in[i];
        __nv_bfloat16 h = __float2bfloat16(v);
        hi[i] = h;
        lo[i] = __float2bfloat16(v - __bfloat162float(h));
    }
}
__global__ void k_splitW2(const float* __restrict__ W0, const float* __restrict__ W1,
                          __nv_bfloat16* __restrict__ hi, __nv_bfloat16* __restrict__ lo,
                          int K, int N) {
    const float* W = blockIdx.y ? W1 : W0;
    size_t off = (size_t)blockIdx.y * N * K;
    int i = blockIdx.x * blockDim.x + threadIdx.x;
    if (i < N * K) {
        int n = i / K, k = i - n * K;
        float v = W[(size_t)k * N + n];
        __nv_bfloat16 h = __float2bfloat16(v);
        hi[off + i] = h;
        lo[off + i] = __float2bfloat16(v - __bfloat162float(h));
    }
}

// ---------------- TMA-fed HMMA dual GEMM with bf16 error-split ----------------
// Term-outer MMA order (acc reuse distance 4). TMA issue kept in its proven
// post-__syncthreads slot (the early-issue hoist deadlocked in R10).
constexpr int TILE_SZ  = 128 * 64;         // 8192 B
constexpr int STAGE_SZ = 4 * TILE_SZ;      // 32768 B
constexpr int NSTAGE   = 3;
constexpr int GEMM_DYN = NSTAGE * STAGE_SZ + 1024 + 64;

__global__ void __launch_bounds__(256, 2)
k_gemm_tma(const __grid_constant__ CUtensorMap tAh, const __grid_constant__ CUtensorMap tAl,
           const __grid_constant__ CUtensorMap tBh, const __grid_constant__ CUtensorMap tBl,
           const float* __restrict__ bias0, const float* __restrict__ bias1,
           float* __restrict__ C0, float* __restrict__ C1,
           int M, int N, int K) {
    extern __shared__ char smem[];
    const uint32_t sraw  = smem_to_u32(smem);
    const uint32_t sbase = (sraw + 1023u) & ~1023u;
    const uint32_t mbars = sbase + NSTAGE * STAGE_SZ;

    const int tid  = threadIdx.x;
    const int lane = tid & 31;
    const int wid  = tid >> 5;
    const int wm   = (wid & 3) * 32;
    const int wn   = (wid >> 2) * 64;
    const int row0 = blockIdx.y * 128;
    const int col0 = blockIdx.x * 128;
    const int brow = (int)blockIdx.z * N + col0;
    const float* bias = blockIdx.z ? bias1 : bias0;
    float*       C    = blockIdx.z ? C1 : C0;

    if (tid == 0) {
#pragma unroll
        for (int s = 0; s < NSTAGE; s++) mbar_init(mbars + s * 8, 1);
    }
    __syncthreads();

    const int nsteps = K / 32;

    auto issue = [&](int s) {
        if (tid == 0) {
            const int buf = s % NSTAGE;
            const uint32_t sb = sbase + buf * STAGE_SZ;
            const uint32_t mb = mbars + buf * 8;
            const int k0 = s * 32;
            mbar_expect(mb, STAGE_SZ);
            tma2d(sb,               &tAh, k0, row0, mb);
            tma2d(sb + TILE_SZ,     &tAl, k0, row0, mb);
            tma2d(sb + 2 * TILE_SZ, &tBh, k0, brow, mb);
            tma2d(sb + 3 * TILE_SZ, &tBl, k0, brow, mb);
        }
    };

    float acc[2][8][4];
#pragma unroll
    for (int mi = 0; mi < 2; mi++)
#pragma unroll
        for (int ni = 0; ni < 8; ni++)
#pragma unroll
            for (int j = 0; j < 4; j++) acc[mi][ni][j] = 0.f;

    issue(0);
    if (nsteps > 1) issue(1);

    int ph[NSTAGE] = {0, 0, 0};

    for (int s = 0; s < nsteps; s++) {
        const int buf = s % NSTAGE;
        mbar_wait(mbars + buf * 8, ph[buf]);
        ph[buf] ^= 1;

        const uint32_t uA  = sbase + buf * STAGE_SZ;
        const uint32_t uAl = uA + TILE_SZ;
        const uint32_t uB  = uA + 2 * TILE_SZ;
        const uint32_t uBl = uA + 3 * TILE_SZ;

#pragma unroll
        for (int ks = 0; ks < 2; ks++) {
            const int kcb = ks * 32;
            uint32_t fAh[2][4], fAl[2][4];
            {
                const int arow = wm + (lane & 15);
                const int acb  = kcb + (lane >> 4) * 16;
#pragma unroll
                for (int mi = 0; mi < 2; mi++) {
                    uint32_t lin = (uint32_t)((arow + mi * 16) * 64 + acb);
                    uint32_t ad  = sw64(lin);
                    ldsm_x4(fAh[mi], uA  + ad);
                    ldsm_x4(fAl[mi], uAl + ad);
                }
            }
            const int br  = (lane & 7) + ((lane >> 4) & 1) * 8;
            const int bcb = kcb + ((lane >> 3) & 1) * 16;
#pragma unroll
            for (int g = 0; g < 4; g++) {
                uint32_t fBh[4], fBl[4];
                uint32_t lin = (uint32_t)((wn + g * 16 + br) * 64 + bcb);
                uint32_t ad  = sw64(lin);
                ldsm_x4(fBh, uB  + ad);
                ldsm_x4(fBl, uBl + ad);
                // term-outer: 4 independent accumulators between reuses
#pragma unroll
                for (int mi = 0; mi < 2; mi++)
#pragma unroll
                    for (int nn = 0; nn < 2; nn++)
                        mma_bf16(acc[mi][g * 2 + nn], fAh[mi], &fBh[nn * 2]);
#pragma unroll
                for (int mi = 0; mi < 2; mi++)
#pragma unroll
                    for (int nn = 0; nn < 2; nn++)
                        mma_bf16(acc[mi][g * 2 + nn], fAh[mi], &fBl[nn * 2]);
#pragma unroll
                for (int mi = 0; mi < 2; mi++)
#pragma unroll
                    for (int nn = 0; nn < 2; nn++)
                        mma_bf16(acc[mi][g * 2 + nn], fAl[mi], &fBh[nn * 2]);
            }
        }
        __syncthreads();
        if (s + 2 < nsteps) issue(s + 2);
    }

    const int g  = lane >> 2;
    const int tg = lane & 3;
#pragma unroll
    for (int mi = 0; mi < 2; mi++) {
        int r0 = row0 + wm + mi * 16 + g;
        int r1 = r0 + 8;
#pragma unroll
        for (int ni = 0; ni < 8; ni++) {
            int cc = col0 + wn + ni * 8 + tg * 2;
            float b0 = bias[cc], b1 = bias[cc + 1];
            if (r0 < M) {
                float2 o = make_float2(acc[mi][ni][0] + b0, acc[mi][ni][1] + b1);
                *(float2*)&C[(size_t)r0 * N + cc] = o;
            }
            if (r1 < M) {
                float2 o = make_float2(acc[mi][ni][2] + b0, acc[mi][ni][3] + b1);
                *(float2*)&C[(size_t)r1 * N + cc] = o;
            }
        }
    }
}

// ---------------- warp-per-(node,head) GATv2 aggregation ----------------
template <int H, int C, bool DO_ELU, bool SPLIT_OUT>
__global__ void __launch_bounds__(128)
k_gat_agg(const float* __restrict__ ew,
          const int*   __restrict__ srcArr,
          const float* __restrict__ We,
          const float* __restrict__ att,
          const float* __restrict__ bias,
          float* __restrict__ outF,
          __nv_bfloat16* __restrict__ outH,
          __nv_bfloat16* __restrict__ outL) {
    constexpr int HC  = H * C;
    constexpr int VPT = C / 32;

    const int wid  = threadIdx.x >> 5;
    const int lane = threadIdx.x & 31;

    int nd, h;
    if constexpr (H == 4) { nd = blockIdx.x; h = wid; }
    else                  { nd = blockIdx.x * 4 + wid; h = 0; if (nd >= NT) return; }
    const int chb = h * C + lane * VPT;

    float rxr[VPT], rWe[VPT], ratt[VPT];
#pragma unroll
    for (int j = 0; j < VPT; j += 4) {
        *(float4*)&rxr[j]  = *(const float4*)&g_XR[(size_t)nd * HC + chb + j];
        *(float4*)&rWe[j]  = *(const float4*)&We[chb + j];
        *(float4*)&ratt[j] = *(const float4*)&att[chb + j];
    }

    const int s0  = g_start[nd];
    const int deg = g_start[nd + 1] - s0;

    float m = -INFINITY, ssum = 0.f;
    float acc[VPT];
#pragma unroll
    for (int j = 0; j < VPT; j++) acc[j] = 0.f;

    int   sQ0 = 0, sQ1 = 0;
    float wQ0 = 0.f, wQ1 = 0.f;
    float xvC[VPT];
    if (deg > 0) { int e = g_csr[s0];     sQ0 = srcArr[e]; wQ0 = ew[e]; }
    if (deg > 1) { int e = g_csr[s0 + 1]; sQ1 = srcArr[e]; wQ1 = ew[e]; }
    if (deg > 0) {
        const float* xp = &g_XL[(size_t)sQ0 * HC + chb];
#pragma unroll
        for (int j = 0; j < VPT; j += 4) *(float4*)&xvC[j] = *(const float4*)(xp + j);
    }

    for (int eo = 0; eo < deg; eo++) {
        int sNN = 0; float wNN = 0.f;
        if (eo + 2 < deg) { int e = g_csr[s0 + eo + 2]; sNN = srcArr[e]; wNN = ew[e]; }
        float xvN[VPT];
        if (eo + 1 < deg) {
            const float* xp = &g_XL[(size_t)sQ1 * HC + chb];
#pragma unroll
            for (int j = 0; j < VPT; j += 4) *(float4*)&xvN[j] = *(const float4*)(xp + j);
        }

        const float w = wQ0;
        float partial = 0.f;
#pragma unroll
        for (int j = 0; j < VPT; j++) {
            float v = xvC[j] + rxr[j] + w * rWe[j];
            v = (v > 0.f) ? v : 0.2f * v;
            partial += v * ratt[j];
        }
#pragma unroll
        for (int off = 16; off; off >>= 1)
            partial += __shfl_xor_sync(0xffffffff, partial, off);
        const float l = partial;

        const float mnew  = fmaxf(m, l);
        const float scale = __expf(m - mnew);
        const float p     = __expf(l - mnew);
        ssum = ssum * scale + p;
#pragma unroll
        for (int j = 0; j < VPT; j++)
            acc[j] = acc[j] * scale + p * xvC[j];
        m = mnew;

#pragma unroll
        for (int j = 0; j < VPT; j++) xvC[j] = xvN[j];
        sQ0 = sQ1; wQ0 = wQ1;
        sQ1 = sNN; wQ1 = wNN;
    }

    const float inv = 1.f / (ssum + 1e-16f);
    const size_t ob = (size_t)nd * HC + chb;
#pragma unroll
    for (int j = 0; j < VPT; j++) {
        float o = acc[j] * inv + bias[chb + j];
        if constexpr (DO_ELU) o = (o > 0.f) ? o : expm1f(o);
        if constexpr (SPLIT_OUT) {
            __nv_bfloat16 hh = __float2bfloat16(o);
            outH[ob + j] = hh;
            outL[ob + j] = __float2bfloat16(o - __bfloat162float(hh));
        } else {
            outF[ob + j] = o;
        }
    }
}

// ---------------- host: tensor-map encode via runtime entry point ----------------
typedef CUresult (*EncodeFn)(CUtensorMap*, CUtensorMapDataType, cuuint32_t, void*,
                             const cuuint64_t*, const cuuint64_t*, const cuuint32_t*,
                             const cuuint32_t*, CUtensorMapInterleave, CUtensorMapSwizzle,
                             CUtensorMapL2promotion, CUtensorMapFloatOOBfill);

static EncodeFn get_encode_fn() {
    static EncodeFn fn = nullptr;
    if (!fn) {
        cudaDriverEntryPointQueryResult st;
        cudaGetDriverEntryPoint("cuTensorMapEncodeTiled", (void**)&fn, cudaEnableDefault, &st);
    }
    return fn;
}

static void make2d(CUtensorMap* m, void* ptr, int K, int rows) {
    cuuint64_t dims[2]    = {(cuuint64_t)K, (cuuint64_t)rows};
    cuuint64_t strides[1] = {(cuuint64_t)K * 2};
    cuuint32_t box[2]     = {32, 128};
    cuuint32_t es[2]      = {1, 1};
    get_encode_fn()(m, CU_TENSOR_MAP_DATA_TYPE_BFLOAT16, 2, ptr, dims, strides, box, es,
                    CU_TENSOR_MAP_INTERLEAVE_NONE, CU_TENSOR_MAP_SWIZZLE_64B,
                    CU_TENSOR_MAP_L2_PROMOTION_L2_128B, CU_TENSOR_MAP_FLOAT_OOB_FILL_NONE);
}

// ---------------- launch ----------------
extern "C" void kernel_launch(void* const* d_in, const int* in_sizes, int n_in,
                              void* d_out, int out_size) {
    const float* x   = (const float*)d_in[0];
    const int*   ei  = (const int*)  d_in[1];
    const float* ew  = (const float*)d_in[2];
    const int* src = ei;
    const int* dst = ei + NE;

    const float *Wl[3], *bl[3], *Wr[3], *br[3], *We[3], *att[3], *bias[3];
    for (int l = 0; l < 3; l++) {
        int b = 3 + 7 * l;
        Wl[l]   = (const float*)d_in[b + 0];
        bl[l]   = (const float*)d_in[b + 1];
        Wr[l]   = (const float*)d_in[b + 2];
        br[l]   = (const float*)d_in[b + 3];
        We[l]   = (const float*)d_in[b + 4];
        att[l]  = (const float*)d_in[b + 5];
        bias[l] = (const float*)d_in[b + 6];
    }

    float *dXL, *dXR;
    __nv_bfloat16 *dAh, *dAl, *dBh, *dBl;
    int *dDeg;
    cudaGetSymbolAddress((void**)&dXL, g_XL);
    cudaGetSymbolAddress((void**)&dXR, g_XR);
    cudaGetSymbolAddress((void**)&dAh, g_Ah);
    cudaGetSymbolAddress((void**)&dAl, g_Al);
    cudaGetSymbolAddress((void**)&dBh, g_Bh);
    cudaGetSymbolAddress((void**)&dBl, g_Bl);
    cudaGetSymbolAddress((void**)&dDeg, g_deg);
    float* dOut = (float*)d_out;

    cudaFuncSetAttribute(k_gemm_tma, cudaFuncAttributeMaxDynamicSharedMemorySize, GEMM_DYN);

    // one-time side stream + events
    static cudaStream_t sside = nullptr;
    static cudaEvent_t evFork = nullptr, evW0 = nullptr, evCsr = nullptr, evW12 = nullptr;
    if (!sside) {
        cudaStreamCreateWithFlags(&sside, cudaStreamNonBlocking);
        cudaEventCreateWithFlags(&evFork, cudaEventDisableTiming);
        cudaEventCreateWithFlags(&evW0,   cudaEventDisableTiming);
        cudaEventCreateWithFlags(&evCsr,  cudaEventDisableTiming);
        cudaEventCreateWithFlags(&evW12,  cudaEventDisableTiming);
    }

    // tensor maps
    CUtensorMap mA64h, mA64l, mA512h, mA512l;
    CUtensorMap mB0h, mB0l, mB1h, mB1l, mB2h, mB2l;
    make2d(&mA64h,  dAh, 64, NT);   make2d(&mA64l,  dAl, 64, NT);
    make2d(&mA512h, dAh, 512, NT);  make2d(&mA512l, dAl, 512, NT);
    make2d(&mB0h, dBh + WOFF0, 64,  2 * 512); make2d(&mB0l, dBl + WOFF0, 64,  2 * 512);
    make2d(&mB1h, dBh + WOFF1, 512, 2 * 512); make2d(&mB1l, dBl + WOFF1, 512, 2 * 512);
    make2d(&mB2h, dBh + WOFF2, 512, 2 * 256); make2d(&mB2l, dBl + WOFF2, 512, 2 * 256);

    const int MB = (NT + 127) / 128;   // 79

    // ---- fork side stream immediately ----
    cudaEventRecord(evFork, 0);
    cudaStreamWaitEvent(sside, evFork, 0);

    k_split<<<(NT * 64 + 255) / 256, 256>>>(x, dAh, dAl, NT * 64);                     // main

    k_splitW2<<<dim3((512 * 64 + 255) / 256, 2), 256, 0, sside>>>(Wl[0], Wr[0],
                                                                  dBh + WOFF0, dBl + WOFF0, 64, 512);
    cudaEventRecord(evW0, sside);
    cudaMemsetAsync(dDeg, 0, NT * sizeof(int), sside);
    k_hist<<<(NE + 255) / 256, 256, 0, sside>>>(dst);

    // ---------- layer 0 GEMM ----------
    cudaStreamWaitEvent(0, evW0, 0);
    k_gemm_tma<<<dim3(512 / 128, MB, 2), 256, GEMM_DYN>>>(mA64h, mA64l, mB0h, mB0l,
                                                          bl[0], br[0], dXL, dXR, NT, 512, 64);

    k_scan   <<<1, 1024, 0, sside>>>();
    k_scatter<<<(NE + 255) / 256, 256, 0, sside>>>(dst);
    cudaEventRecord(evCsr, sside);
    k_splitW2<<<dim3((512 * 512 + 255) / 256, 2), 256, 0, sside>>>(Wl[1], Wr[1],
                                                                   dBh + WOFF1, dBl + WOFF1, 512, 512);
    k_splitW2<<<dim3((256 * 512 + 255) / 256, 2), 256, 0, sside>>>(Wl[2], Wr[2],
                                                                   dBh + WOFF2, dBl + WOFF2, 512, 256);
    cudaEventRecord(evW12, sside);

    // ---------- layer 0 aggregate ----------
    cudaStreamWaitEvent(0, evCsr, 0);
    k_gat_agg<4, 128, true, true><<<NT, 128>>>(ew, src, We[0], att[0], bias[0],
                                               nullptr, dAh, dAl);

    // ---------- layer 1 ----------
    cudaStreamWaitEvent(0, evW12, 0);
    k_gemm_tma<<<dim3(512 / 128, MB, 2), 256, GEMM_DYN>>>(mA512h, mA512l, mB1h, mB1l,
                                                          bl[1], br[1], dXL, dXR, NT, 512, 512);
    k_gat_agg<4, 128, true, true><<<NT, 128>>>(ew, src, We[1], att[1], bias[1],
                                               nullptr, dAh, dAl);

    // ---------- layer 2 ----------
    k_gemm_tma<<<dim3(256 / 128, MB, 2), 256, GEMM_DYN>>>(mA512h, mA512l, mB2h, mB2l,
                                                          bl[2], br[2], dXL, dXR, NT, 256, 512);
    k_gat_agg<1, 256, false, false><<<(NT + 3) / 4, 128>>>(ew, src, We[2], att[2], bias[2],
                                                           dOut, nullptr, nullptr);
}

// round 14
// speedup vs baseline: 1.0697x; 1.0479x over previous
#include <cuda_runtime.h>
#include <cuda.h>
#include <cuda_bf16.h>
#include <math.h>
#include <cstdint>

// ---------------- problem constants ----------------
#define NT 10000      // total nodes
#define NE 120000     // edges
#define HCMAX 512

// per-layer weight-buffer offsets (elements) in g_Bh/g_Bl
#define WOFF0 0                 // layer0: 2*512*64  = 65536
#define WOFF1 65536             // layer1: 2*512*512 = 524288
#define WOFF2 589824            // layer2: 2*256*512 = 262144
#define WTOT  851968

// ---------------- device scratch ----------------
__device__ float g_XL[NT * HCMAX];
__device__ float g_XR[NT * HCMAX];
__device__ __nv_bfloat16 g_Ah[NT * HCMAX];
__device__ __nv_bfloat16 g_Al[NT * HCMAX];
__device__ __nv_bfloat16 g_Bh[WTOT];
__device__ __nv_bfloat16 g_Bl[WTOT];
__device__ int   g_deg[NT];
__device__ int   g_start[NT + 1];
__device__ int   g_cursor[NT];
__device__ int   g_csr[NE];

// ---------------- device helpers ----------------
__device__ __forceinline__ uint32_t smem_to_u32(const void* p) {
    uint32_t a;
    asm("{ .reg .u64 t; cvta.to.shared.u64 t, %1; cvt.u32.u64 %0, t; }" : "=r"(a) : "l"(p));
    return a;
}
__device__ __forceinline__ void ldsm_x4(uint32_t* r, uint32_t addr) {
    asm volatile("ldmatrix.sync.aligned.m8n8.x4.shared.b16 {%0,%1,%2,%3}, [%4];"
                 : "=r"(r[0]), "=r"(r[1]), "=r"(r[2]), "=r"(r[3]) : "r"(addr));
}
__device__ __forceinline__ void mma_bf16(float* c, const uint32_t* a, const uint32_t* b) {
    asm volatile("mma.sync.aligned.m16n8k16.row.col.f32.bf16.bf16.f32 "
                 "{%0,%1,%2,%3}, {%4,%5,%6,%7}, {%8,%9}, {%0,%1,%2,%3};"
                 : "+f"(c[0]), "+f"(c[1]), "+f"(c[2]), "+f"(c[3])
                 : "r"(a[0]), "r"(a[1]), "r"(a[2]), "r"(a[3]), "r"(b[0]), "r"(b[1]));
}
__device__ __forceinline__ void tma2d(uint32_t smem, const CUtensorMap* m, int x, int y, uint32_t mb) {
    asm volatile("cp.async.bulk.tensor.2d.shared::cta.global.tile.mbarrier::complete_tx::bytes "
                 "[%0], [%1, {%2, %3}], [%4];"
                 :: "r"(smem), "l"(m), "r"(x), "r"(y), "r"(mb) : "memory");
}
__device__ __forceinline__ void mbar_init(uint32_t mb, uint32_t cnt) {
    asm volatile("mbarrier.init.shared.b64 [%0], %1;" :: "r"(mb), "r"(cnt) : "memory");
}
__device__ __forceinline__ void mbar_expect(uint32_t mb, uint32_t bytes) {
    asm volatile("mbarrier.arrive.expect_tx.shared.b64 _, [%0], %1;" :: "r"(mb), "r"(bytes) : "memory");
}
__device__ __forceinline__ void mbar_arrive(uint32_t mb) {
    asm volatile("mbarrier.arrive.shared.b64 _, [%0];" :: "r"(mb) : "memory");
}
__device__ __forceinline__ void mbar_wait(uint32_t mb, uint32_t par) {
    uint32_t done;
    asm volatile("{ .reg .pred p; mbarrier.try_wait.parity.acquire.cta.shared::cta.b64 p, [%1], %2;"
                 " selp.b32 %0, 1, 0, p; }" : "=r"(done) : "r"(mb), "r"(par) : "memory");
    if (!done) {
        asm volatile("{ .reg .pred P1; WL_%=: mbarrier.try_wait.parity.acquire.cta.shared::cta.b64 P1, [%0], %1, 0x989680;"
                     " @P1 bra.uni WD_%=; bra.uni WL_%=; WD_%=: }"
                     :: "r"(mb), "r"(par) : "memory");
    }
}
__device__ __forceinline__ uint32_t sw64(uint32_t o) { return o ^ ((o >> 3) & 0x30); }

// ---------------- CSR build ----------------
__global__ void k_hist(const int* __restrict__ dst) {
    int e = blockIdx.x * blockDim.x + threadIdx.x;
    if (e < NE) atomicAdd(&g_deg[dst[e]], 1);
}
__global__ void __launch_bounds__(1024) k_scan() {
    __shared__ int sh[1024];
    const int CH = (NT + 1023) / 1024;   // 10
    int tid = threadIdx.x;
    int base = tid * CH;
    int loc[10];
    int s = 0;
#pragma unroll
    for (int i = 0; i < 10; i++) {
        int n = base + i;
        int d = (i < CH && n < NT) ? g_deg[n] : 0;
        loc[i] = d;
        s += d;
    }
    sh[tid] = s;
    __syncthreads();
    for (int off = 1; off < 1024; off <<= 1) {
        int v = (tid >= off) ? sh[tid - off] : 0;
        __syncthreads();
        sh[tid] += v;
        __syncthreads();
    }
    int run = sh[tid] - s;
#pragma unroll
    for (int i = 0; i < 10; i++) {
        int n = base + i;
        if (i < CH && n < NT) {
            g_start[n]  = run;
            g_cursor[n] = run;
            run += loc[i];
        }
    }
    if (tid == 1023) g_start[NT] = sh[1023];
}
__global__ void k_scatter(const int* __restrict__ dst) {
    int e = blockIdx.x * blockDim.x + threadIdx.x;
    if (e < NE) {
        int p = atomicAdd(&g_cursor[dst[e]], 1);
        g_csr[p] = e;
    }
}

// ---------------- fp32 -> bf16 hi/lo split ----------------
__global__ void k_split(const float* __restrict__ in, __nv_bfloat16* __restrict__ hi,
                        __nv_bfloat16* __restrict__ lo, int n) {
    int i = blockIdx.x * blockDim.x + threadIdx.x;
    if (i < n) {
        float v = in[i];
        __nv_bfloat16 h = __float2bfloat16(v);
        hi[i] = h;
        lo[i] = __float2bfloat16(v - __bfloat162float(h));
    }
}
__global__ void k_splitW2(const float* __restrict__ W0, const float* __restrict__ W1,
                          __nv_bfloat16* __restrict__ hi, __nv_bfloat16* __restrict__ lo,
                          int K, int N) {
    const float* W = blockIdx.y ? W1 : W0;
    size_t off = (size_t)blockIdx.y * N * K;
    int i = blockIdx.x * blockDim.x + threadIdx.x;
    if (i < N * K) {
        int n = i / K, k = i - n * K;
        float v = W[(size_t)k * N + n];
        __nv_bfloat16 h = __float2bfloat16(v);
        hi[off + i] = h;
        lo[off + i] = __float2bfloat16(v - __bfloat162float(h));
    }
}

// ---------------- TMA-fed HMMA dual GEMM with bf16 error-split ----------------
// Free-running full/empty mbarrier pipeline: no __syncthreads in the mainloop.
// full[buf]: tx-barrier (TMA completion). empty[buf]: 8 warp-arrivals gate reissue.
constexpr int TILE_SZ  = 128 * 64;         // 8192 B
constexpr int STAGE_SZ = 4 * TILE_SZ;      // 32768 B
constexpr int NSTAGE   = 3;
constexpr int GEMM_DYN = NSTAGE * STAGE_SZ + 1024 + 64;

__global__ void __launch_bounds__(256, 2)
k_gemm_tma(const __grid_constant__ CUtensorMap tAh, const __grid_constant__ CUtensorMap tAl,
           const __grid_constant__ CUtensorMap tBh, const __grid_constant__ CUtensorMap tBl,
           const float* __restrict__ bias0, const float* __restrict__ bias1,
           float* __restrict__ C0, float* __restrict__ C1,
           int M, int N, int K) {
    extern __shared__ char smem[];
    const uint32_t sraw  = smem_to_u32(smem);
    const uint32_t sbase = (sraw + 1023u) & ~1023u;
    const uint32_t fullb  = sbase + NSTAGE * STAGE_SZ;        // 3 x 8B
    const uint32_t emptyb = fullb + NSTAGE * 8;               // 3 x 8B

    const int tid  = threadIdx.x;
    const int lane = tid & 31;
    const int wid  = tid >> 5;
    const int wm   = (wid & 3) * 32;
    const int wn   = (wid >> 2) * 64;
    const int row0 = blockIdx.y * 128;
    const int col0 = blockIdx.x * 128;
    const int brow = (int)blockIdx.z * N + col0;
    const float* bias = blockIdx.z ? bias1 : bias0;
    float*       C    = blockIdx.z ? C1 : C0;

    if (tid == 0) {
#pragma unroll
        for (int s = 0; s < NSTAGE; s++) {
            mbar_init(fullb  + s * 8, 1);
            mbar_init(emptyb + s * 8, 8);   // one arrival per warp
        }
    }
    __syncthreads();

    const int nsteps = K / 32;

    auto issue = [&](int s) {
        const int buf = s % NSTAGE;
        const uint32_t sb = sbase + buf * STAGE_SZ;
        const uint32_t mb = fullb + buf * 8;
        const int k0 = s * 32;
        mbar_expect(mb, STAGE_SZ);
        tma2d(sb,               &tAh, k0, row0, mb);
        tma2d(sb + TILE_SZ,     &tAl, k0, row0, mb);
        tma2d(sb + 2 * TILE_SZ, &tBh, k0, brow, mb);
        tma2d(sb + 3 * TILE_SZ, &tBl, k0, brow, mb);
    };

    float acc[2][8][4];
#pragma unroll
    for (int mi = 0; mi < 2; mi++)
#pragma unroll
        for (int ni = 0; ni < 8; ni++)
#pragma unroll
            for (int j = 0; j < 4; j++) acc[mi][ni][j] = 0.f;

    if (tid == 0) {
        issue(0);
        if (nsteps > 1) issue(1);
    }

    int phF[NSTAGE] = {0, 0, 0};
    int phE[NSTAGE] = {0, 0, 0};

    for (int s = 0; s < nsteps; s++) {
        const int buf = s % NSTAGE;

        // producer: reissue buffer (s+2)%NSTAGE once all 8 warps released it
        if (tid == 0 && s + 2 < nsteps) {
            const int nb = (s + 2) % NSTAGE;
            if (s + 2 >= NSTAGE) {          // buffer previously used -> wait release
                mbar_wait(emptyb + nb * 8, phE[nb]);
                phE[nb] ^= 1;
            }
            issue(s + 2);
        }

        // consumer: wait stage data
        mbar_wait(fullb + buf * 8, phF[buf]);
        phF[buf] ^= 1;

        const uint32_t uA  = sbase + buf * STAGE_SZ;
        const uint32_t uAl = uA + TILE_SZ;
        const uint32_t uB  = uA + 2 * TILE_SZ;
        const uint32_t uBl = uA + 3 * TILE_SZ;

#pragma unroll
        for (int ks = 0; ks < 2; ks++) {
            const int kcb = ks * 32;
            uint32_t fAh[2][4], fAl[2][4];
            {
                const int arow = wm + (lane & 15);
                const int acb  = kcb + (lane >> 4) * 16;
#pragma unroll
                for (int mi = 0; mi < 2; mi++) {
                    uint32_t lin = (uint32_t)((arow + mi * 16) * 64 + acb);
                    uint32_t ad  = sw64(lin);
                    ldsm_x4(fAh[mi], uA  + ad);
                    ldsm_x4(fAl[mi], uAl + ad);
                }
            }
            const int br  = (lane & 7) + ((lane >> 4) & 1) * 8;
            const int bcb = kcb + ((lane >> 3) & 1) * 16;
#pragma unroll
            for (int g = 0; g < 4; g++) {
                uint32_t fBh[4], fBl[4];
                uint32_t lin = (uint32_t)((wn + g * 16 + br) * 64 + bcb);
                uint32_t ad  = sw64(lin);
                ldsm_x4(fBh, uB  + ad);
                ldsm_x4(fBl, uBl + ad);
#pragma unroll
                for (int mi = 0; mi < 2; mi++)
#pragma unroll
                    for (int nn = 0; nn < 2; nn++)
                        mma_bf16(acc[mi][g * 2 + nn], fAh[mi], &fBh[nn * 2]);
#pragma unroll
                for (int mi = 0; mi < 2; mi++)
#pragma unroll
                    for (int nn = 0; nn < 2; nn++)
                        mma_bf16(acc[mi][g * 2 + nn], fAh[mi], &fBl[nn * 2]);
#pragma unroll
                for (int mi = 0; mi < 2; mi++)
#pragma unroll
                    for (int nn = 0; nn < 2; nn++)
                        mma_bf16(acc[mi][g * 2 + nn], fAl[mi], &fBh[nn * 2]);
            }
        }

        // release the stage: one arrival per warp (reads are complete)
        if (lane == 0) mbar_arrive(emptyb + buf * 8);
    }

    const int g  = lane >> 2;
    const int tg = lane & 3;
#pragma unroll
    for (int mi = 0; mi < 2; mi++) {
        int r0 = row0 + wm + mi * 16 + g;
        int r1 = r0 + 8;
#pragma unroll
        for (int ni = 0; ni < 8; ni++) {
            int cc = col0 + wn + ni * 8 + tg * 2;
            float b0 = bias[cc], b1 = bias[cc + 1];
            if (r0 < M) {
                float2 o = make_float2(acc[mi][ni][0] + b0, acc[mi][ni][1] + b1);
                *(float2*)&C[(size_t)r0 * N + cc] = o;
            }
            if (r1 < M) {
                float2 o = make_float2(acc[mi][ni][2] + b0, acc[mi][ni][3] + b1);
                *(float2*)&C[(size_t)r1 * N + cc] = o;
            }
        }
    }
}

// ---------------- warp-per-(node,head) GATv2 aggregation ----------------
template <int H, int C, bool DO_ELU, bool SPLIT_OUT>
__global__ void __launch_bounds__(128)
k_gat_agg(const float* __restrict__ ew,
          const int*   __restrict__ srcArr,
          const float* __restrict__ We,
          const float* __restrict__ att,
          const float* __restrict__ bias,
          float* __restrict__ outF,
          __nv_bfloat16* __restrict__ outH,
          __nv_bfloat16* __restrict__ outL) {
    constexpr int HC  = H * C;
    constexpr int VPT = C / 32;

    const int wid  = threadIdx.x >> 5;
    const int lane = threadIdx.x & 31;

    int nd, h;
    if constexpr (H == 4) { nd = blockIdx.x; h = wid; }
    else                  { nd = blockIdx.x * 4 + wid; h = 0; if (nd >= NT) return; }
    const int chb = h * C + lane * VPT;

    float rxr[VPT], rWe[VPT], ratt[VPT];
#pragma unroll
    for (int j = 0; j < VPT; j += 4) {
        *(float4*)&rxr[j]  = *(const float4*)&g_XR[(size_t)nd * HC + chb + j];
        *(float4*)&rWe[j]  = *(const float4*)&We[chb + j];
        *(float4*)&ratt[j] = *(const float4*)&att[chb + j];
    }

    const int s0  = g_start[nd];
    const int deg = g_start[nd + 1] - s0;

    float m = -INFINITY, ssum = 0.f;
    float acc[VPT];
#pragma unroll
    for (int j = 0; j < VPT; j++) acc[j] = 0.f;

    int   sQ0 = 0, sQ1 = 0;
    float wQ0 = 0.f, wQ1 = 0.f;
    float xvC[VPT];
    if (deg > 0) { int e = g_csr[s0];     sQ0 = srcArr[e]; wQ0 = ew[e]; }
    if (deg > 1) { int e = g_csr[s0 + 1]; sQ1 = srcArr[e]; wQ1 = ew[e]; }
    if (deg > 0) {
        const float* xp = &g_XL[(size_t)sQ0 * HC + chb];
#pragma unroll
        for (int j = 0; j < VPT; j += 4) *(float4*)&xvC[j] = *(const float4*)(xp + j);
    }

    for (int eo = 0; eo < deg; eo++) {
        int sNN = 0; float wNN = 0.f;
        if (eo + 2 < deg) { int e = g_csr[s0 + eo + 2]; sNN = srcArr[e]; wNN = ew[e]; }
        float xvN[VPT];
        if (eo + 1 < deg) {
            const float* xp = &g_XL[(size_t)sQ1 * HC + chb];
#pragma unroll
            for (int j = 0; j < VPT; j += 4) *(float4*)&xvN[j] = *(const float4*)(xp + j);
        }

        const float w = wQ0;
        float partial = 0.f;
#pragma unroll
        for (int j = 0; j < VPT; j++) {
            float v = xvC[j] + rxr[j] + w * rWe[j];
            v = (v > 0.f) ? v : 0.2f * v;
            partial += v * ratt[j];
        }
#pragma unroll
        for (int off = 16; off; off >>= 1)
            partial += __shfl_xor_sync(0xffffffff, partial, off);
        const float l = partial;

        const float mnew  = fmaxf(m, l);
        const float scale = __expf(m - mnew);
        const float p     = __expf(l - mnew);
        ssum = ssum * scale + p;
#pragma unroll
        for (int j = 0; j < VPT; j++)
            acc[j] = acc[j] * scale + p * xvC[j];
        m = mnew;

#pragma unroll
        for (int j = 0; j < VPT; j++) xvC[j] = xvN[j];
        sQ0 = sQ1; wQ0 = wQ1;
        sQ1 = sNN; wQ1 = wNN;
    }

    const float inv = 1.f / (ssum + 1e-16f);
    const size_t ob = (size_t)nd * HC + chb;
#pragma unroll
    for (int j = 0; j < VPT; j++) {
        float o = acc[j] * inv + bias[chb + j];
        if constexpr (DO_ELU) o = (o > 0.f) ? o : expm1f(o);
        if constexpr (SPLIT_OUT) {
            __nv_bfloat16 hh = __float2bfloat16(o);
            outH[ob + j] = hh;
            outL[ob + j] = __float2bfloat16(o - __bfloat162float(hh));
        } else {
            outF[ob + j] = o;
        }
    }
}

// ---------------- host: tensor-map encode via runtime entry point ----------------
typedef CUresult (*EncodeFn)(CUtensorMap*, CUtensorMapDataType, cuuint32_t, void*,
                             const cuuint64_t*, const cuuint64_t*, const cuuint32_t*,
                             const cuuint32_t*, CUtensorMapInterleave, CUtensorMapSwizzle,
                             CUtensorMapL2promotion, CUtensorMapFloatOOBfill);

static EncodeFn get_encode_fn() {
    static EncodeFn fn = nullptr;
    if (!fn) {
        cudaDriverEntryPointQueryResult st;
        cudaGetDriverEntryPoint("cuTensorMapEncodeTiled", (void**)&fn, cudaEnableDefault, &st);
    }
    return fn;
}

static void make2d(CUtensorMap* m, void* ptr, int K, int rows) {
    cuuint64_t dims[2]    = {(cuuint64_t)K, (cuuint64_t)rows};
    cuuint64_t strides[1] = {(cuuint64_t)K * 2};
    cuuint32_t box[2]     = {32, 128};
    cuuint32_t es[2]      = {1, 1};
    get_encode_fn()(m, CU_TENSOR_MAP_DATA_TYPE_BFLOAT16, 2, ptr, dims, strides, box, es,
                    CU_TENSOR_MAP_INTERLEAVE_NONE, CU_TENSOR_MAP_SWIZZLE_64B,
                    CU_TENSOR_MAP_L2_PROMOTION_L2_128B, CU_TENSOR_MAP_FLOAT_OOB_FILL_NONE);
}

// ---------------- launch ----------------
extern "C" void kernel_launch(void* const* d_in, const int* in_sizes, int n_in,
                              void* d_out, int out_size) {
    const float* x   = (const float*)d_in[0];
    const int*   ei  = (const int*)  d_in[1];
    const float* ew  = (const float*)d_in[2];
    const int* src = ei;
    const int* dst = ei + NE;

    const float *Wl[3], *bl[3], *Wr[3], *br[3], *We[3], *att[3], *bias[3];
    for (int l = 0; l < 3; l++) {
        int b = 3 + 7 * l;
        Wl[l]   = (const float*)d_in[b + 0];
        bl[l]   = (const float*)d_in[b + 1];
        Wr[l]   = (const float*)d_in[b + 2];
        br[l]   = (const float*)d_in[b + 3];
        We[l]   = (const float*)d_in[b + 4];
        att[l]  = (const float*)d_in[b + 5];
        bias[l] = (const float*)d_in[b + 6];
    }

    float *dXL, *dXR;
    __nv_bfloat16 *dAh, *dAl, *dBh, *dBl;
    int *dDeg;
    cudaGetSymbolAddress((void**)&dXL, g_XL);
    cudaGetSymbolAddress((void**)&dXR, g_XR);
    cudaGetSymbolAddress((void**)&dAh, g_Ah);
    cudaGetSymbolAddress((void**)&dAl, g_Al);
    cudaGetSymbolAddress((void**)&dBh, g_Bh);
    cudaGetSymbolAddress((void**)&dBl, g_Bl);
    cudaGetSymbolAddress((void**)&dDeg, g_deg);
    float* dOut = (float*)d_out;

    cudaFuncSetAttribute(k_gemm_tma, cudaFuncAttributeMaxDynamicSharedMemorySize, GEMM_DYN);

    // one-time side stream + events
    static cudaStream_t sside = nullptr;
    static cudaEvent_t evFork = nullptr, evW0 = nullptr, evCsr = nullptr, evW12 = nullptr;
    if (!sside) {
        cudaStreamCreateWithFlags(&sside, cudaStreamNonBlocking);
        cudaEventCreateWithFlags(&evFork, cudaEventDisableTiming);
        cudaEventCreateWithFlags(&evW0,   cudaEventDisableTiming);
        cudaEventCreateWithFlags(&evCsr,  cudaEventDisableTiming);
        cudaEventCreateWithFlags(&evW12,  cudaEventDisableTiming);
    }

    // tensor maps
    CUtensorMap mA64h, mA64l, mA512h, mA512l;
    CUtensorMap mB0h, mB0l, mB1h, mB1l, mB2h, mB2l;
    make2d(&mA64h,  dAh, 64, NT);   make2d(&mA64l,  dAl, 64, NT);
    make2d(&mA512h, dAh, 512, NT);  make2d(&mA512l, dAl, 512, NT);
    make2d(&mB0h, dBh + WOFF0, 64,  2 * 512); make2d(&mB0l, dBl + WOFF0, 64,  2 * 512);
    make2d(&mB1h, dBh + WOFF1, 512, 2 * 512); make2d(&mB1l, dBl + WOFF1, 512, 2 * 512);
    make2d(&mB2h, dBh + WOFF2, 512, 2 * 256); make2d(&mB2l, dBl + WOFF2, 512, 2 * 256);

    const int MB = (NT + 127) / 128;   // 79

    // ---- fork side stream immediately ----
    cudaEventRecord(evFork, 0);
    cudaStreamWaitEvent(sside, evFork, 0);

    k_split<<<(NT * 64 + 255) / 256, 256>>>(x, dAh, dAl, NT * 64);                     // main

    k_splitW2<<<dim3((512 * 64 + 255) / 256, 2), 256, 0, sside>>>(Wl[0], Wr[0],
                                                                  dBh + WOFF0, dBl + WOFF0, 64, 512);
    cudaEventRecord(evW0, sside);
    cudaMemsetAsync(dDeg, 0, NT * sizeof(int), sside);
    k_hist<<<(NE + 255) / 256, 256, 0, sside>>>(dst);

    // ---------- layer 0 GEMM ----------
    cudaStreamWaitEvent(0, evW0, 0);
    k_gemm_tma<<<dim3(512 / 128, MB, 2), 256, GEMM_DYN>>>(mA64h, mA64l, mB0h, mB0l,
                                                          bl[0], br[0], dXL, dXR, NT, 512, 64);

    k_scan   <<<1, 1024, 0, sside>>>();
    k_scatter<<<(NE + 255) / 256, 256, 0, sside>>>(dst);
    cudaEventRecord(evCsr, sside);
    k_splitW2<<<dim3((512 * 512 + 255) / 256, 2), 256, 0, sside>>>(Wl[1], Wr[1],
                                                                   dBh + WOFF1, dBl + WOFF1, 512, 512);
    k_splitW2<<<dim3((256 * 512 + 255) / 256, 2), 256, 0, sside>>>(Wl[2], Wr[2],
                                                                   dBh + WOFF2, dBl + WOFF2, 512, 256);
    cudaEventRecord(evW12, sside);

    // ---------- layer 0 aggregate ----------
    cudaStreamWaitEvent(0, evCsr, 0);
    k_gat_agg<4, 128, true, true><<<NT, 128>>>(ew, src, We[0], att[0], bias[0],
                                               nullptr, dAh, dAl);

    // ---------- layer 1 ----------
    cudaStreamWaitEvent(0, evW12, 0);
    k_gemm_tma<<<dim3(512 / 128, MB, 2), 256, GEMM_DYN>>>(mA512h, mA512l, mB1h, mB1l,
                                                          bl[1], br[1], dXL, dXR, NT, 512, 512);
    k_gat_agg<4, 128, true, true><<<NT, 128>>>(ew, src, We[1], att[1], bias[1],
                                               nullptr, dAh, dAl);

    // ---------- layer 2 ----------
    k_gemm_tma<<<dim3(256 / 128, MB, 2), 256, GEMM_DYN>>>(mA512h, mA512l, mB2h, mB2l,
                                                          bl[2], br[2], dXL, dXR, NT, 256, 512);
    k_gat_agg<1, 256, false, false><<<(NT + 3) / 4, 128>>>(ew, src, We[2], att[2], bias[2],
                                                           dOut, nullptr, nullptr);
}

// round 15
// speedup vs baseline: 1.1834x; 1.1063x over previous
#include <cuda_runtime.h>
#include <cuda.h>
#include <cuda_fp16.h>
#include <math.h>
#include <cstdint>

// ---------------- problem constants ----------------
#define NT 10000      // total nodes
#define NE 120000     // edges
#define HCMAX 512

// per-layer weight-buffer offsets (elements) in g_Bh (fp16, [z][N][K])
#define WOFF0 0                 // layer0: 2*512*64  = 65536
#define WOFF1 65536             // layer1: 2*512*512 = 524288
#define WOFF2 589824            // layer2: 2*256*512 = 262144
#define WTOT  851968

// ---------------- device scratch ----------------
__device__ float g_XL[NT * HCMAX];
__device__ float g_XR[NT * HCMAX];
__device__ __half g_Ah[NT * HCMAX];
__device__ __half g_Al[NT * HCMAX];
__device__ __half g_Bh[WTOT];
__device__ int   g_deg[NT];
__device__ int   g_start[NT + 1];
__device__ int   g_cursor[NT];
__device__ int   g_csr[NE];

// ---------------- device helpers ----------------
__device__ __forceinline__ uint32_t smem_to_u32(const void* p) {
    uint32_t a;
    asm("{ .reg .u64 t; cvta.to.shared.u64 t, %1; cvt.u32.u64 %0, t; }" : "=r"(a) : "l"(p));
    return a;
}
__device__ __forceinline__ void ldsm_x4(uint32_t* r, uint32_t addr) {
    asm volatile("ldmatrix.sync.aligned.m8n8.x4.shared.b16 {%0,%1,%2,%3}, [%4];"
                 : "=r"(r[0]), "=r"(r[1]), "=r"(r[2]), "=r"(r[3]) : "r"(addr));
}
__device__ __forceinline__ void mma_f16(float* c, const uint32_t* a, const uint32_t* b) {
    asm volatile("mma.sync.aligned.m16n8k16.row.col.f32.f16.f16.f32 "
                 "{%0,%1,%2,%3}, {%4,%5,%6,%7}, {%8,%9}, {%0,%1,%2,%3};"
                 : "+f"(c[0]), "+f"(c[1]), "+f"(c[2]), "+f"(c[3])
                 : "r"(a[0]), "r"(a[1]), "r"(a[2]), "r"(a[3]), "r"(b[0]), "r"(b[1]));
}
__device__ __forceinline__ void tma2d(uint32_t smem, const CUtensorMap* m, int x, int y, uint32_t mb) {
    asm volatile("cp.async.bulk.tensor.2d.shared::cta.global.tile.mbarrier::complete_tx::bytes "
                 "[%0], [%1, {%2, %3}], [%4];"
                 :: "r"(smem), "l"(m), "r"(x), "r"(y), "r"(mb) : "memory");
}
__device__ __forceinline__ void mbar_init(uint32_t mb, uint32_t cnt) {
    asm volatile("mbarrier.init.shared.b64 [%0], %1;" :: "r"(mb), "r"(cnt) : "memory");
}
__device__ __forceinline__ void mbar_expect(uint32_t mb, uint32_t bytes) {
    asm volatile("mbarrier.arrive.expect_tx.shared.b64 _, [%0], %1;" :: "r"(mb), "r"(bytes) : "memory");
}
__device__ __forceinline__ void mbar_arrive(uint32_t mb) {
    asm volatile("mbarrier.arrive.shared.b64 _, [%0];" :: "r"(mb) : "memory");
}
__device__ __forceinline__ void mbar_wait(uint32_t mb, uint32_t par) {
    uint32_t done;
    asm volatile("{ .reg .pred p; mbarrier.try_wait.parity.acquire.cta.shared::cta.b64 p, [%1], %2;"
                 " selp.b32 %0, 1, 0, p; }" : "=r"(done) : "r"(mb), "r"(par) : "memory");
    if (!done) {
        asm volatile("{ .reg .pred P1; WL_%=: mbarrier.try_wait.parity.acquire.cta.shared::cta.b64 P1, [%0], %1, 0x989680;"
                     " @P1 bra.uni WD_%=; bra.uni WL_%=; WD_%=: }"
                     :: "r"(mb), "r"(par) : "memory");
    }
}
__device__ __forceinline__ uint32_t sw64(uint32_t o) { return o ^ ((o >> 3) & 0x30); }

// ---------------- CSR build ----------------
__global__ void k_hist(const int* __restrict__ dst) {
    int e = blockIdx.x * blockDim.x + threadIdx.x;
    if (e < NE) atomicAdd(&g_deg[dst[e]], 1);
}
__global__ void __launch_bounds__(1024) k_scan() {
    __shared__ int sh[1024];
    const int CH = (NT + 1023) / 1024;   // 10
    int tid = threadIdx.x;
    int base = tid * CH;
    int loc[10];
    int s = 0;
#pragma unroll
    for (int i = 0; i < 10; i++) {
        int n = base + i;
        int d = (i < CH && n < NT) ? g_deg[n] : 0;
        loc[i] = d;
        s += d;
    }
    sh[tid] = s;
    __syncthreads();
    for (int off = 1; off < 1024; off <<= 1) {
        int v = (tid >= off) ? sh[tid - off] : 0;
        __syncthreads();
        sh[tid] += v;
        __syncthreads();
    }
    int run = sh[tid] - s;
#pragma unroll
    for (int i = 0; i < 10; i++) {
        int n = base + i;
        if (i < CH && n < NT) {
            g_start[n]  = run;
            g_cursor[n] = run;
            run += loc[i];
        }
    }
    if (tid == 1023) g_start[NT] = sh[1023];
}
__global__ void k_scatter(const int* __restrict__ dst) {
    int e = blockIdx.x * blockDim.x + threadIdx.x;
    if (e < NE) {
        int p = atomicAdd(&g_cursor[dst[e]], 1);
        g_csr[p] = e;
    }
}

// ---------------- fp32 -> fp16 hi/lo split (activations) ----------------
__global__ void k_split(const float* __restrict__ in, __half* __restrict__ hi,
                        __half* __restrict__ lo, int n) {
    int i = blockIdx.x * blockDim.x + threadIdx.x;
    if (i < n) {
        float v = in[i];
        __half h = __float2half(v);
        hi[i] = h;
        lo[i] = __float2half(v - __half2float(h));
    }
}
// W [K,N] row-major -> Wt [N,K] single fp16, both Wl (y=0) and Wr (y=1)
__global__ void k_splitWh(const float* __restrict__ W0, const float* __restrict__ W1,
                          __half* __restrict__ out, int K, int N) {
    const float* W = blockIdx.y ? W1 : W0;
    size_t off = (size_t)blockIdx.y * N * K;
    int i = blockIdx.x * blockDim.x + threadIdx.x;
    if (i < N * K) {
        int n = i / K, k = i - n * K;
        out[off + i] = __float2half(W[(size_t)k * N + n]);
    }
}

// ---------------- TMA-fed HMMA dual GEMM, fp16 2-term split ----------------
// C = (Ah+Al) @ Bh^T + bias.  Stage = Ah tile + Al tile + B tile (3 x 8KB).
// Free-running full/empty mbarrier pipeline, NSTAGE=4, lookahead 3.
constexpr int TILE_SZ  = 128 * 64;         // 8192 B
constexpr int STAGE_SZ = 3 * TILE_SZ;      // 24576 B
constexpr int NSTAGE   = 4;
constexpr int LOOKA    = NSTAGE - 1;       // 3
constexpr int GEMM_DYN = NSTAGE * STAGE_SZ + 1024 + 128;

__global__ void __launch_bounds__(256, 2)
k_gemm_tma(const __grid_constant__ CUtensorMap tAh, const __grid_constant__ CUtensorMap tAl,
           const __grid_constant__ CUtensorMap tBh,
           const float* __restrict__ bias0, const float* __restrict__ bias1,
           float* __restrict__ C0, float* __restrict__ C1,
           int M, int N, int K) {
    extern __shared__ char smem[];
    const uint32_t sraw  = smem_to_u32(smem);
    const uint32_t sbase = (sraw + 1023u) & ~1023u;
    const uint32_t fullb  = sbase + NSTAGE * STAGE_SZ;        // 4 x 8B
    const uint32_t emptyb = fullb + NSTAGE * 8;               // 4 x 8B

    const int tid  = threadIdx.x;
    const int lane = tid & 31;
    const int wid  = tid >> 5;
    const int wm   = (wid & 3) * 32;
    const int wn   = (wid >> 2) * 64;
    const int row0 = blockIdx.y * 128;
    const int col0 = blockIdx.x * 128;
    const int brow = (int)blockIdx.z * N + col0;
    const float* bias = blockIdx.z ? bias1 : bias0;
    float*       C    = blockIdx.z ? C1 : C0;

    if (tid == 0) {
#pragma unroll
        for (int s = 0; s < NSTAGE; s++) {
            mbar_init(fullb  + s * 8, 1);
            mbar_init(emptyb + s * 8, 8);   // one arrival per warp
        }
    }
    __syncthreads();

    const int nsteps = K / 32;

    auto issue = [&](int s) {
        const int buf = s % NSTAGE;
        const uint32_t sb = sbase + buf * STAGE_SZ;
        const uint32_t mb = fullb + buf * 8;
        const int k0 = s * 32;
        mbar_expect(mb, STAGE_SZ);
        tma2d(sb,               &tAh, k0, row0, mb);
        tma2d(sb + TILE_SZ,     &tAl, k0, row0, mb);
        tma2d(sb + 2 * TILE_SZ, &tBh, k0, brow, mb);
    };

    float acc[2][8][4];
#pragma unroll
    for (int mi = 0; mi < 2; mi++)
#pragma unroll
        for (int ni = 0; ni < 8; ni++)
#pragma unroll
            for (int j = 0; j < 4; j++) acc[mi][ni][j] = 0.f;

    if (tid == 0) {
#pragma unroll
        for (int s = 0; s < LOOKA; s++)
            if (s < nsteps) issue(s);
    }

    int phF[NSTAGE] = {0, 0, 0, 0};
    int phE[NSTAGE] = {0, 0, 0, 0};

    for (int s = 0; s < nsteps; s++) {
        const int buf = s % NSTAGE;

        // producer: reissue buffer (s+LOOKA)%NSTAGE once all warps released it
        if (tid == 0 && s + LOOKA < nsteps) {
            const int nb = (s + LOOKA) % NSTAGE;
            if (s + LOOKA >= NSTAGE) {
                mbar_wait(emptyb + nb * 8, phE[nb]);
                phE[nb] ^= 1;
            }
            issue(s + LOOKA);
        }

        mbar_wait(fullb + buf * 8, phF[buf]);
        phF[buf] ^= 1;

        const uint32_t uA  = sbase + buf * STAGE_SZ;
        const uint32_t uAl = uA + TILE_SZ;
        const uint32_t uB  = uA + 2 * TILE_SZ;

#pragma unroll
        for (int ks = 0; ks < 2; ks++) {
            const int kcb = ks * 32;
            uint32_t fAh[2][4], fAl[2][4];
            {
                const int arow = wm + (lane & 15);
                const int acb  = kcb + (lane >> 4) * 16;
#pragma unroll
                for (int mi = 0; mi < 2; mi++) {
                    uint32_t lin = (uint32_t)((arow + mi * 16) * 64 + acb);
                    uint32_t ad  = sw64(lin);
                    ldsm_x4(fAh[mi], uA  + ad);
                    ldsm_x4(fAl[mi], uAl + ad);
                }
            }
            const int br  = (lane & 7) + ((lane >> 4) & 1) * 8;
            const int bcb = kcb + ((lane >> 3) & 1) * 16;
#pragma unroll
            for (int g = 0; g < 4; g++) {
                uint32_t fBh[4];
                uint32_t lin = (uint32_t)((wn + g * 16 + br) * 64 + bcb);
                uint32_t ad  = sw64(lin);
                ldsm_x4(fBh, uB + ad);
#pragma unroll
                for (int mi = 0; mi < 2; mi++)
#pragma unroll
                    for (int nn = 0; nn < 2; nn++)
                        mma_f16(acc[mi][g * 2 + nn], fAh[mi], &fBh[nn * 2]);
#pragma unroll
                for (int mi = 0; mi < 2; mi++)
#pragma unroll
                    for (int nn = 0; nn < 2; nn++)
                        mma_f16(acc[mi][g * 2 + nn], fAl[mi], &fBh[nn * 2]);
            }
        }

        if (lane == 0) mbar_arrive(emptyb + buf * 8);
    }

    const int g  = lane >> 2;
    const int tg = lane & 3;
#pragma unroll
    for (int mi = 0; mi < 2; mi++) {
        int r0 = row0 + wm + mi * 16 + g;
        int r1 = r0 + 8;
#pragma unroll
        for (int ni = 0; ni < 8; ni++) {
            int cc = col0 + wn + ni * 8 + tg * 2;
            float b0 = bias[cc], b1 = bias[cc + 1];
            if (r0 < M) {
                float2 o = make_float2(acc[mi][ni][0] + b0, acc[mi][ni][1] + b1);
                *(float2*)&C[(size_t)r0 * N + cc] = o;
            }
            if (r1 < M) {
                float2 o = make_float2(acc[mi][ni][2] + b0, acc[mi][ni][3] + b1);
                *(float2*)&C[(size_t)r1 * N + cc] = o;
            }
        }
    }
}

// ---------------- warp-per-(node,head) GATv2 aggregation ----------------
template <int H, int C, bool DO_ELU, bool SPLIT_OUT>
__global__ void __launch_bounds__(128)
k_gat_agg(const float* __restrict__ ew,
          const int*   __restrict__ srcArr,
          const float* __restrict__ We,
          const float* __restrict__ att,
          const float* __restrict__ bias,
          float* __restrict__ outF,
          __half* __restrict__ outH,
          __half* __restrict__ outL) {
    constexpr int HC  = H * C;
    constexpr int VPT = C / 32;

    const int wid  = threadIdx.x >> 5;
    const int lane = threadIdx.x & 31;

    int nd, h;
    if constexpr (H == 4) { nd = blockIdx.x; h = wid; }
    else                  { nd = blockIdx.x * 4 + wid; h = 0; if (nd >= NT) return; }
    const int chb = h * C + lane * VPT;

    float rxr[VPT], rWe[VPT], ratt[VPT];
#pragma unroll
    for (int j = 0; j < VPT; j += 4) {
        *(float4*)&rxr[j]  = *(const float4*)&g_XR[(size_t)nd * HC + chb + j];
        *(float4*)&rWe[j]  = *(const float4*)&We[chb + j];
        *(float4*)&ratt[j] = *(const float4*)&att[chb + j];
    }

    const int s0  = g_start[nd];
    const int deg = g_start[nd + 1] - s0;

    float m = -INFINITY, ssum = 0.f;
    float acc[VPT];
#pragma unroll
    for (int j = 0; j < VPT; j++) acc[j] = 0.f;

    int   sQ0 = 0, sQ1 = 0;
    float wQ0 = 0.f, wQ1 = 0.f;
    float xvC[VPT];
    if (deg > 0) { int e = g_csr[s0];     sQ0 = srcArr[e]; wQ0 = ew[e]; }
    if (deg > 1) { int e = g_csr[s0 + 1]; sQ1 = srcArr[e]; wQ1 = ew[e]; }
    if (deg > 0) {
        const float* xp = &g_XL[(size_t)sQ0 * HC + chb];
#pragma unroll
        for (int j = 0; j < VPT; j += 4) *(float4*)&xvC[j] = *(const float4*)(xp + j);
    }

    for (int eo = 0; eo < deg; eo++) {
        int sNN = 0; float wNN = 0.f;
        if (eo + 2 < deg) { int e = g_csr[s0 + eo + 2]; sNN = srcArr[e]; wNN = ew[e]; }
        float xvN[VPT];
        if (eo + 1 < deg) {
            const float* xp = &g_XL[(size_t)sQ1 * HC + chb];
#pragma unroll
            for (int j = 0; j < VPT; j += 4) *(float4*)&xvN[j] = *(const float4*)(xp + j);
        }

        const float w = wQ0;
        float partial = 0.f;
#pragma unroll
        for (int j = 0; j < VPT; j++) {
            float v = xvC[j] + rxr[j] + w * rWe[j];
            v = (v > 0.f) ? v : 0.2f * v;
            partial += v * ratt[j];
        }
#pragma unroll
        for (int off = 16; off; off >>= 1)
            partial += __shfl_xor_sync(0xffffffff, partial, off);
        const float l = partial;

        const float mnew  = fmaxf(m, l);
        const float scale = __expf(m - mnew);
        const float p     = __expf(l - mnew);
        ssum = ssum * scale + p;
#pragma unroll
        for (int j = 0; j < VPT; j++)
            acc[j] = acc[j] * scale + p * xvC[j];
        m = mnew;

#pragma unroll
        for (int j = 0; j < VPT; j++) xvC[j] = xvN[j];
        sQ0 = sQ1; wQ0 = wQ1;
        sQ1 = sNN; wQ1 = wNN;
    }

    const float inv = 1.f / (ssum + 1e-16f);
    const size_t ob = (size_t)nd * HC + chb;
#pragma unroll
    for (int j = 0; j < VPT; j++) {
        float o = acc[j] * inv + bias[chb + j];
        if constexpr (DO_ELU) o = (o > 0.f) ? o : expm1f(o);
        if constexpr (SPLIT_OUT) {
            __half hh = __float2half(o);
            outH[ob + j] = hh;
            outL[ob + j] = __float2half(o - __half2float(hh));
        } else {
            outF[ob + j] = o;
        }
    }
}

// ---------------- host: tensor-map encode via runtime entry point ----------------
typedef CUresult (*EncodeFn)(CUtensorMap*, CUtensorMapDataType, cuuint32_t, void*,
                             const cuuint64_t*, const cuuint64_t*, const cuuint32_t*,
                             const cuuint32_t*, CUtensorMapInterleave, CUtensorMapSwizzle,
                             CUtensorMapL2promotion, CUtensorMapFloatOOBfill);

static EncodeFn get_encode_fn() {
    static EncodeFn fn = nullptr;
    if (!fn) {
        cudaDriverEntryPointQueryResult st;
        cudaGetDriverEntryPoint("cuTensorMapEncodeTiled", (void**)&fn, cudaEnableDefault, &st);
    }
    return fn;
}

static void make2d(CUtensorMap* m, void* ptr, int K, int rows) {
    cuuint64_t dims[2]    = {(cuuint64_t)K, (cuuint64_t)rows};
    cuuint64_t strides[1] = {(cuuint64_t)K * 2};
    cuuint32_t box[2]     = {32, 128};
    cuuint32_t es[2]      = {1, 1};
    get_encode_fn()(m, CU_TENSOR_MAP_DATA_TYPE_FLOAT16, 2, ptr, dims, strides, box, es,
                    CU_TENSOR_MAP_INTERLEAVE_NONE, CU_TENSOR_MAP_SWIZZLE_64B,
                    CU_TENSOR_MAP_L2_PROMOTION_L2_128B, CU_TENSOR_MAP_FLOAT_OOB_FILL_NONE);
}

// ---------------- launch ----------------
extern "C" void kernel_launch(void* const* d_in, const int* in_sizes, int n_in,
                              void* d_out, int out_size) {
    const float* x   = (const float*)d_in[0];
    const int*   ei  = (const int*)  d_in[1];
    const float* ew  = (const float*)d_in[2];
    const int* src = ei;
    const int* dst = ei + NE;

    const float *Wl[3], *bl[3], *Wr[3], *br[3], *We[3], *att[3], *bias[3];
    for (int l = 0; l < 3; l++) {
        int b = 3 + 7 * l;
        Wl[l]   = (const float*)d_in[b + 0];
        bl[l]   = (const float*)d_in[b + 1];
        Wr[l]   = (const float*)d_in[b + 2];
        br[l]   = (const float*)d_in[b + 3];
        We[l]   = (const float*)d_in[b + 4];
        att[l]  = (const float*)d_in[b + 5];
        bias[l] = (const float*)d_in[b + 6];
    }

    float *dXL, *dXR;
    __half *dAh, *dAl, *dBh;
    int *dDeg;
    cudaGetSymbolAddress((void**)&dXL, g_XL);
    cudaGetSymbolAddress((void**)&dXR, g_XR);
    cudaGetSymbolAddress((void**)&dAh, g_Ah);
    cudaGetSymbolAddress((void**)&dAl, g_Al);
    cudaGetSymbolAddress((void**)&dBh, g_Bh);
    cudaGetSymbolAddress((void**)&dDeg, g_deg);
    float* dOut = (float*)d_out;

    cudaFuncSetAttribute(k_gemm_tma, cudaFuncAttributeMaxDynamicSharedMemorySize, GEMM_DYN);

    // one-time side stream + events
    static cudaStream_t sside = nullptr;
    static cudaEvent_t evFork = nullptr, evW0 = nullptr, evCsr = nullptr, evW12 = nullptr;
    if (!sside) {
        cudaStreamCreateWithFlags(&sside, cudaStreamNonBlocking);
        cudaEventCreateWithFlags(&evFork, cudaEventDisableTiming);
        cudaEventCreateWithFlags(&evW0,   cudaEventDisableTiming);
        cudaEventCreateWithFlags(&evCsr,  cudaEventDisableTiming);
        cudaEventCreateWithFlags(&evW12,  cudaEventDisableTiming);
    }

    // tensor maps
    CUtensorMap mA64h, mA64l, mA512h, mA512l;
    CUtensorMap mB0, mB1, mB2;
    make2d(&mA64h,  dAh, 64, NT);   make2d(&mA64l,  dAl, 64, NT);
    make2d(&mA512h, dAh, 512, NT);  make2d(&mA512l, dAl, 512, NT);
    make2d(&mB0, dBh + WOFF0, 64,  2 * 512);
    make2d(&mB1, dBh + WOFF1, 512, 2 * 512);
    make2d(&mB2, dBh + WOFF2, 512, 2 * 256);

    const int MB = (NT + 127) / 128;   // 79

    // ---- fork side stream immediately ----
    cudaEventRecord(evFork, 0);
    cudaStreamWaitEvent(sside, evFork, 0);

    k_split<<<(NT * 64 + 255) / 256, 256>>>(x, dAh, dAl, NT * 64);                     // main

    k_splitWh<<<dim3((512 * 64 + 255) / 256, 2), 256, 0, sside>>>(Wl[0], Wr[0],
                                                                  dBh + WOFF0, 64, 512);
    cudaEventRecord(evW0, sside);
    cudaMemsetAsync(dDeg, 0, NT * sizeof(int), sside);
    k_hist<<<(NE + 255) / 256, 256, 0, sside>>>(dst);

    // ---------- layer 0 GEMM ----------
    cudaStreamWaitEvent(0, evW0, 0);
    k_gemm_tma<<<dim3(512 / 128, MB, 2), 256, GEMM_DYN>>>(mA64h, mA64l, mB0,
                                                          bl[0], br[0], dXL, dXR, NT, 512, 64);

    k_scan   <<<1, 1024, 0, sside>>>();
    k_scatter<<<(NE + 255) / 256, 256, 0, sside>>>(dst);
    cudaEventRecord(evCsr, sside);
    k_splitWh<<<dim3((512 * 512 + 255) / 256, 2), 256, 0, sside>>>(Wl[1], Wr[1],
                                                                   dBh + WOFF1, 512, 512);
    k_splitWh<<<dim3((256 * 512 + 255) / 256, 2), 256, 0, sside>>>(Wl[2], Wr[2],
                                                                   dBh + WOFF2, 512, 256);
    cudaEventRecord(evW12, sside);

    // ---------- layer 0 aggregate ----------
    cudaStreamWaitEvent(0, evCsr, 0);
    k_gat_agg<4, 128, true, true><<<NT, 128>>>(ew, src, We[0], att[0], bias[0],
                                               nullptr, dAh, dAl);

    // ---------- layer 1 ----------
    cudaStreamWaitEvent(0, evW12, 0);
    k_gemm_tma<<<dim3(512 / 128, MB, 2), 256, GEMM_DYN>>>(mA512h, mA512l, mB1,
                                                          bl[1], br[1], dXL, dXR, NT, 512, 512);
    k_gat_agg<4, 128, true, true><<<NT, 128>>>(ew, src, We[1], att[1], bias[1],
                                               nullptr, dAh, dAl);

    // ---------- layer 2 ----------
    k_gemm_tma<<<dim3(256 / 128, MB, 2), 256, GEMM_DYN>>>(mA512h, mA512l, mB2,
                                                          bl[2], br[2], dXL, dXR, NT, 256, 512);
    k_gat_agg<1, 256, false, false><<<(NT + 3) / 4, 128>>>(ew, src, We[2], att[2], bias[2],
                                                           dOut, nullptr, nullptr);
}

// round 17
// speedup vs baseline: 1.1926x; 1.0078x over previous
#include <cuda_runtime.h>
#include <cuda.h>
#include <cuda_fp16.h>
#include <math.h>
#include <cstdint>

// ---------------- problem constants ----------------
#define NT 10000      // total nodes
#define NE 120000     // edges
#define HCMAX 512

// per-layer weight-buffer offsets (elements) in g_Bh (fp16, [z][N][K])
#define WOFF0 0                 // layer0: 2*512*64  = 65536
#define WOFF1 65536             // layer1: 2*512*512 = 524288
#define WOFF2 589824            // layer2: 2*256*512 = 262144
#define WTOT  851968

// ---------------- device scratch ----------------
__device__ __half g_XL[NT * HCMAX];   // fp16 now: halves agg gather traffic
__device__ __half g_XR[NT * HCMAX];
__device__ __half g_Ah[NT * HCMAX];
__device__ __half g_Al[NT * HCMAX];
__device__ __half g_Bh[WTOT];
__device__ int   g_deg[NT];
__device__ int   g_start[NT + 1];
__device__ int   g_cursor[NT];
__device__ int   g_csr[NE];

// ---------------- device helpers ----------------
__device__ __forceinline__ uint32_t smem_to_u32(const void* p) {
    uint32_t a;
    asm("{ .reg .u64 t; cvta.to.shared.u64 t, %1; cvt.u32.u64 %0, t; }" : "=r"(a) : "l"(p));
    return a;
}
__device__ __forceinline__ void ldsm_x4(uint32_t* r, uint32_t addr) {
    asm volatile("ldmatrix.sync.aligned.m8n8.x4.shared.b16 {%0,%1,%2,%3}, [%4];"
                 : "=r"(r[0]), "=r"(r[1]), "=r"(r[2]), "=r"(r[3]) : "r"(addr));
}
__device__ __forceinline__ void mma_f16(float* c, const uint32_t* a, const uint32_t* b) {
    asm volatile("mma.sync.aligned.m16n8k16.row.col.f32.f16.f16.f32 "
                 "{%0,%1,%2,%3}, {%4,%5,%6,%7}, {%8,%9}, {%0,%1,%2,%3};"
                 : "+f"(c[0]), "+f"(c[1]), "+f"(c[2]), "+f"(c[3])
                 : "r"(a[0]), "r"(a[1]), "r"(a[2]), "r"(a[3]), "r"(b[0]), "r"(b[1]));
}
__device__ __forceinline__ void tma2d(uint32_t smem, const CUtensorMap* m, int x, int y, uint32_t mb) {
    asm volatile("cp.async.bulk.tensor.2d.shared::cta.global.tile.mbarrier::complete_tx::bytes "
                 "[%0], [%1, {%2, %3}], [%4];"
                 :: "r"(smem), "l"(m), "r"(x), "r"(y), "r"(mb) : "memory");
}
__device__ __forceinline__ void mbar_init(uint32_t mb, uint32_t cnt) {
    asm volatile("mbarrier.init.shared.b64 [%0], %1;" :: "r"(mb), "r"(cnt) : "memory");
}
__device__ __forceinline__ void mbar_expect(uint32_t mb, uint32_t bytes) {
    asm volatile("mbarrier.arrive.expect_tx.shared.b64 _, [%0], %1;" :: "r"(mb), "r"(bytes) : "memory");
}
__device__ __forceinline__ void mbar_arrive(uint32_t mb) {
    asm volatile("mbarrier.arrive.shared.b64 _, [%0];" :: "r"(mb) : "memory");
}
__device__ __forceinline__ void mbar_wait(uint32_t mb, uint32_t par) {
    uint32_t done;
    asm volatile("{ .reg .pred p; mbarrier.try_wait.parity.acquire.cta.shared::cta.b64 p, [%1], %2;"
                 " selp.b32 %0, 1, 0, p; }" : "=r"(done) : "r"(mb), "r"(par) : "memory");
    if (!done) {
        asm volatile("{ .reg .pred P1; WL_%=: mbarrier.try_wait.parity.acquire.cta.shared::cta.b64 P1, [%0], %1, 0x989680;"
                     " @P1 bra.uni WD_%=; bra.uni WL_%=; WD_%=: }"
                     :: "r"(mb), "r"(par) : "memory");
    }
}
__device__ __forceinline__ uint32_t sw64(uint32_t o) { return o ^ ((o >> 3) & 0x30); }

// vectorized half -> float loads
__device__ __forceinline__ void ldh4(const __half* p, float* o) {
    uint2 v = *(const uint2*)p;
    float2 a = __half22float2(*(__half2*)&v.x);
    float2 b = __half22float2(*(__half2*)&v.y);
    o[0] = a.x; o[1] = a.y; o[2] = b.x; o[3] = b.y;
}
__device__ __forceinline__ void ldh8(const __half* p, float* o) {
    uint4 v = *(const uint4*)p;
    float2 a = __half22float2(*(__half2*)&v.x);
    float2 b = __half22float2(*(__half2*)&v.y);
    float2 c = __half22float2(*(__half2*)&v.z);
    float2 d = __half22float2(*(__half2*)&v.w);
    o[0] = a.x; o[1] = a.y; o[2] = b.x; o[3] = b.y;
    o[4] = c.x; o[5] = c.y; o[6] = d.x; o[7] = d.y;
}

// ---------------- CSR build ----------------
__global__ void k_hist(const int* __restrict__ dst) {
    int e = blockIdx.x * blockDim.x + threadIdx.x;
    if (e < NE) atomicAdd(&g_deg[dst[e]], 1);
}
__global__ void __launch_bounds__(1024) k_scan() {
    __shared__ int sh[1024];
    const int CH = (NT + 1023) / 1024;   // 10
    int tid = threadIdx.x;
    int base = tid * CH;
    int loc[10];
    int s = 0;
#pragma unroll
    for (int i = 0; i < 10; i++) {
        int n = base + i;
        int d = (i < CH && n < NT) ? g_deg[n] : 0;
        loc[i] = d;
        s += d;
    }
    sh[tid] = s;
    __syncthreads();
    for (int off = 1; off < 1024; off <<= 1) {
        int v = (tid >= off) ? sh[tid - off] : 0;
        __syncthreads();
        sh[tid] += v;
        __syncthreads();
    }
    int run = sh[tid] - s;
#pragma unroll
    for (int i = 0; i < 10; i++) {
        int n = base + i;
        if (i < CH && n < NT) {
            g_start[n]  = run;
            g_cursor[n] = run;
            run += loc[i];
        }
    }
    if (tid == 1023) g_start[NT] = sh[1023];
}
__global__ void k_scatter(const int* __restrict__ dst) {
    int e = blockIdx.x * blockDim.x + threadIdx.x;
    if (e < NE) {
        int p = atomicAdd(&g_cursor[dst[e]], 1);
        g_csr[p] = e;
    }
}

// ---------------- fp32 -> fp16 hi/lo split (activations) ----------------
__global__ void k_split(const float* __restrict__ in, __half* __restrict__ hi,
                        __half* __restrict__ lo, int n) {
    int i = blockIdx.x * blockDim.x + threadIdx.x;
    if (i < n) {
        float v = in[i];
        __half h = __float2half(v);
        hi[i] = h;
        lo[i] = __float2half(v - __half2float(h));
    }
}
// W [K,N] row-major -> Wt [N,K] single fp16, both Wl (y=0) and Wr (y=1)
__global__ void k_splitWh(const float* __restrict__ W0, const float* __restrict__ W1,
                          __half* __restrict__ out, int K, int N) {
    const float* W = blockIdx.y ? W1 : W0;
    size_t off = (size_t)blockIdx.y * N * K;
    int i = blockIdx.x * blockDim.x + threadIdx.x;
    if (i < N * K) {
        int n = i / K, k = i - n * K;
        out[off + i] = __float2half(W[(size_t)k * N + n]);
    }
}

// ---------------- TMA-fed HMMA dual GEMM, fp16 2-term split ----------------
constexpr int TILE_SZ  = 128 * 64;         // 8192 B
constexpr int STAGE_SZ = 3 * TILE_SZ;      // 24576 B
constexpr int NSTAGE   = 4;
constexpr int LOOKA    = NSTAGE - 1;       // 3
constexpr int GEMM_DYN = NSTAGE * STAGE_SZ + 1024 + 128;

__global__ void __launch_bounds__(256, 2)
k_gemm_tma(const __grid_constant__ CUtensorMap tAh, const __grid_constant__ CUtensorMap tAl,
           const __grid_constant__ CUtensorMap tBh,
           const float* __restrict__ bias0, const float* __restrict__ bias1,
           __half* __restrict__ C0, __half* __restrict__ C1,
           int M, int N, int K) {
    extern __shared__ char smem[];
    const uint32_t sraw  = smem_to_u32(smem);
    const uint32_t sbase = (sraw + 1023u) & ~1023u;
    const uint32_t fullb  = sbase + NSTAGE * STAGE_SZ;
    const uint32_t emptyb = fullb + NSTAGE * 8;

    const int tid  = threadIdx.x;
    const int lane = tid & 31;
    const int wid  = tid >> 5;
    const int wm   = (wid & 3) * 32;
    const int wn   = (wid >> 2) * 64;
    const int row0 = blockIdx.y * 128;
    const int col0 = blockIdx.x * 128;
    const int brow = (int)blockIdx.z * N + col0;
    const float* bias = blockIdx.z ? bias1 : bias0;
    __half*      C    = blockIdx.z ? C1 : C0;

    if (tid == 0) {
#pragma unroll
        for (int s = 0; s < NSTAGE; s++) {
            mbar_init(fullb  + s * 8, 1);
            mbar_init(emptyb + s * 8, 8);
        }
    }
    __syncthreads();

    const int nsteps = K / 32;

    auto issue = [&](int s) {
        const int buf = s % NSTAGE;
        const uint32_t sb = sbase + buf * STAGE_SZ;
        const uint32_t mb = fullb + buf * 8;
        const int k0 = s * 32;
        mbar_expect(mb, STAGE_SZ);
        tma2d(sb,               &tAh, k0, row0, mb);
        tma2d(sb + TILE_SZ,     &tAl, k0, row0, mb);
        tma2d(sb + 2 * TILE_SZ, &tBh, k0, brow, mb);
    };

    float acc[2][8][4];
#pragma unroll
    for (int mi = 0; mi < 2; mi++)
#pragma unroll
        for (int ni = 0; ni < 8; ni++)
#pragma unroll
            for (int j = 0; j < 4; j++) acc[mi][ni][j] = 0.f;

    if (tid == 0) {
#pragma unroll
        for (int s = 0; s < LOOKA; s++)
            if (s < nsteps) issue(s);
    }

    int phF[NSTAGE] = {0, 0, 0, 0};
    int phE[NSTAGE] = {0, 0, 0, 0};

    for (int s = 0; s < nsteps; s++) {
        const int buf = s % NSTAGE;

        if (tid == 0 && s + LOOKA < nsteps) {
            const int nb = (s + LOOKA) % NSTAGE;
            if (s + LOOKA >= NSTAGE) {
                mbar_wait(emptyb + nb * 8, phE[nb]);
                phE[nb] ^= 1;
            }
            issue(s + LOOKA);
        }

        mbar_wait(fullb + buf * 8, phF[buf]);
        phF[buf] ^= 1;

        const uint32_t uA  = sbase + buf * STAGE_SZ;
        const uint32_t uAl = uA + TILE_SZ;
        const uint32_t uB  = uA + 2 * TILE_SZ;

#pragma unroll
        for (int ks = 0; ks < 2; ks++) {
            const int kcb = ks * 32;
            uint32_t fAh[2][4], fAl[2][4];
            {
                const int arow = wm + (lane & 15);
                const int acb  = kcb + (lane >> 4) * 16;
#pragma unroll
                for (int mi = 0; mi < 2; mi++) {
                    uint32_t lin = (uint32_t)((arow + mi * 16) * 64 + acb);
                    uint32_t ad  = sw64(lin);
                    ldsm_x4(fAh[mi], uA  + ad);
                    ldsm_x4(fAl[mi], uAl + ad);
                }
            }
            const int br  = (lane & 7) + ((lane >> 4) & 1) * 8;
            const int bcb = kcb + ((lane >> 3) & 1) * 16;
#pragma unroll
            for (int g = 0; g < 4; g++) {
                uint32_t fBh[4];
                uint32_t lin = (uint32_t)((wn + g * 16 + br) * 64 + bcb);
                uint32_t ad  = sw64(lin);
                ldsm_x4(fBh, uB + ad);
#pragma unroll
                for (int mi = 0; mi < 2; mi++)
#pragma unroll
                    for (int nn = 0; nn < 2; nn++)
                        mma_f16(acc[mi][g * 2 + nn], fAh[mi], &fBh[nn * 2]);
#pragma unroll
                for (int mi = 0; mi < 2; mi++)
#pragma unroll
                    for (int nn = 0; nn < 2; nn++)
                        mma_f16(acc[mi][g * 2 + nn], fAl[mi], &fBh[nn * 2]);
            }
        }

        if (lane == 0) mbar_arrive(emptyb + buf * 8);
    }

    // epilogue: bias + fp16 store
    const int g  = lane >> 2;
    const int tg = lane & 3;
#pragma unroll
    for (int mi = 0; mi < 2; mi++) {
        int r0 = row0 + wm + mi * 16 + g;
        int r1 = r0 + 8;
#pragma unroll
        for (int ni = 0; ni < 8; ni++) {
            int cc = col0 + wn + ni * 8 + tg * 2;
            float b0 = bias[cc], b1 = bias[cc + 1];
            if (r0 < M) {
                __half2 o = __floats2half2_rn(acc[mi][ni][0] + b0, acc[mi][ni][1] + b1);
                *(__half2*)&C[(size_t)r0 * N + cc] = o;
            }
            if (r1 < M) {
                __half2 o = __floats2half2_rn(acc[mi][ni][2] + b0, acc[mi][ni][3] + b1);
                *(__half2*)&C[(size_t)r1 * N + cc] = o;
            }
        }
    }
}

// ---------------- warp-per-(node,head) GATv2 aggregation (fp16 XL/XR) ----------------
template <int H, int C, bool DO_ELU, bool SPLIT_OUT>
__global__ void __launch_bounds__(128)
k_gat_agg(const float* __restrict__ ew,
          const int*   __restrict__ srcArr,
          const float* __restrict__ We,
          const float* __restrict__ att,
          const float* __restrict__ bias,
          float* __restrict__ outF,
          __half* __restrict__ outH,
          __half* __restrict__ outL) {
    constexpr int HC  = H * C;
    constexpr int VPT = C / 32;           // 4 (H=4) or 8 (H=1)

    const int wid  = threadIdx.x >> 5;
    const int lane = threadIdx.x & 31;

    int nd, h;
    if constexpr (H == 4) { nd = blockIdx.x; h = wid; }
    else                  { nd = blockIdx.x * 4 + wid; h = 0; if (nd >= NT) return; }
    const int chb = h * C + lane * VPT;

    float rxr[VPT], rWe[VPT], ratt[VPT];
    if constexpr (VPT == 4) ldh4(&g_XR[(size_t)nd * HC + chb], rxr);
    else                    ldh8(&g_XR[(size_t)nd * HC + chb], rxr);
#pragma unroll
    for (int j = 0; j < VPT; j += 4) {
        *(float4*)&rWe[j]  = *(const float4*)&We[chb + j];
        *(float4*)&ratt[j] = *(const float4*)&att[chb + j];
    }

    const int s0  = g_start[nd];
    const int deg = g_start[nd + 1] - s0;

    float m = -INFINITY, ssum = 0.f;
    float acc[VPT];
#pragma unroll
    for (int j = 0; j < VPT; j++) acc[j] = 0.f;

    int   sQ0 = 0, sQ1 = 0;
    float wQ0 = 0.f, wQ1 = 0.f;
    float xvC[VPT];
    if (deg > 0) { int e = g_csr[s0];     sQ0 = srcArr[e]; wQ0 = ew[e]; }
    if (deg > 1) { int e = g_csr[s0 + 1]; sQ1 = srcArr[e]; wQ1 = ew[e]; }
    if (deg > 0) {
        const __half* xp = &g_XL[(size_t)sQ0 * HC + chb];
        if constexpr (VPT == 4) ldh4(xp, xvC); else ldh8(xp, xvC);
    }

    for (int eo = 0; eo < deg; eo++) {
        int sNN = 0; float wNN = 0.f;
        if (eo + 2 < deg) { int e = g_csr[s0 + eo + 2]; sNN = srcArr[e]; wNN = ew[e]; }
        float xvN[VPT];
        if (eo + 1 < deg) {
            const __half* xp = &g_XL[(size_t)sQ1 * HC + chb];
            if constexpr (VPT == 4) ldh4(xp, xvN); else ldh8(xp, xvN);
        }

        const float w = wQ0;
        float partial = 0.f;
#pragma unroll
        for (int j = 0; j < VPT; j++) {
            float v = xvC[j] + rxr[j] + w * rWe[j];
            v = (v > 0.f) ? v : 0.2f * v;
            partial += v * ratt[j];
        }
#pragma unroll
        for (int off = 16; off; off >>= 1)
            partial += __shfl_xor_sync(0xffffffff, partial, off);
        const float l = partial;

        const float mnew  = fmaxf(m, l);
        const float scale = __expf(m - mnew);
        const float p     = __expf(l - mnew);
        ssum = ssum * scale + p;
#pragma unroll
        for (int j = 0; j < VPT; j++)
            acc[j] = acc[j] * scale + p * xvC[j];
        m = mnew;

#pragma unroll
        for (int j = 0; j < VPT; j++) xvC[j] = xvN[j];
        sQ0 = sQ1; wQ0 = wQ1;
        sQ1 = sNN; wQ1 = wNN;
    }

    const float inv = 1.f / (ssum + 1e-16f);
    const size_t ob = (size_t)nd * HC + chb;
#pragma unroll
    for (int j = 0; j < VPT; j++) {
        float o = acc[j] * inv + bias[chb + j];
        if constexpr (DO_ELU) o = (o > 0.f) ? o : expm1f(o);
        if constexpr (SPLIT_OUT) {
            __half hh = __float2half(o);
            outH[ob + j] = hh;
            outL[ob + j] = __float2half(o - __half2float(hh));
        } else {
            outF[ob + j] = o;
        }
    }
}

// ---------------- host: tensor-map encode via runtime entry point ----------------
typedef CUresult (*EncodeFn)(CUtensorMap*, CUtensorMapDataType, cuuint32_t, void*,
                             const cuuint64_t*, const cuuint64_t*, const cuuint32_t*,
                             const cuuint32_t*, CUtensorMapInterleave, CUtensorMapSwizzle,
                             CUtensorMapL2promotion, CUtensorMapFloatOOBfill);

static EncodeFn get_encode_fn() {
    static EncodeFn fn = nullptr;
    if (!fn) {
        cudaDriverEntryPointQueryResult st;
        cudaGetDriverEntryPoint("cuTensorMapEncodeTiled", (void**)&fn, cudaEnableDefault, &st);
    }
    return fn;
}

static void make2d(CUtensorMap* m, void* ptr, int K, int rows) {
    cuuint64_t dims[2]    = {(cuuint64_t)K, (cuuint64_t)rows};
    cuuint64_t strides[1] = {(cuuint64_t)K * 2};
    cuuint32_t box[2]     = {32, 128};
    cuuint32_t es[2]      = {1, 1};
    get_encode_fn()(m, CU_TENSOR_MAP_DATA_TYPE_FLOAT16, 2, ptr, dims, strides, box, es,
                    CU_TENSOR_MAP_INTERLEAVE_NONE, CU_TENSOR_MAP_SWIZZLE_64B,
                    CU_TENSOR_MAP_L2_PROMOTION_L2_128B, CU_TENSOR_MAP_FLOAT_OOB_FILL_NONE);
}

// ---------------- launch ----------------
extern "C" void kernel_launch(void* const* d_in, const int* in_sizes, int n_in,
                              void* d_out, int out_size) {
    const float* x   = (const float*)d_in[0];
    const int*   ei  = (const int*)  d_in[1];
    const float* ew  = (const float*)d_in[2];
    const int* src = ei;
    const int* dst = ei + NE;

    const float *Wl[3], *bl[3], *Wr[3], *br[3], *We[3], *att[3], *bias[3];
    for (int l = 0; l < 3; l++) {
        int b = 3 + 7 * l;
        Wl[l]   = (const float*)d_in[b + 0];
        bl[l]   = (const float*)d_in[b + 1];
        Wr[l]   = (const float*)d_in[b + 2];
        br[l]   = (const float*)d_in[b + 3];
        We[l]   = (const float*)d_in[b + 4];
        att[l]  = (const float*)d_in[b + 5];
        bias[l] = (const float*)d_in[b + 6];
    }

    __half *dXL, *dXR, *dAh, *dAl, *dBh;
    int *dDeg;
    cudaGetSymbolAddress((void**)&dXL, g_XL);
    cudaGetSymbolAddress((void**)&dXR, g_XR);
    cudaGetSymbolAddress((void**)&dAh, g_Ah);
    cudaGetSymbolAddress((void**)&dAl, g_Al);
    cudaGetSymbolAddress((void**)&dBh, g_Bh);
    cudaGetSymbolAddress((void**)&dDeg, g_deg);
    float* dOut = (float*)d_out;

    cudaFuncSetAttribute(k_gemm_tma, cudaFuncAttributeMaxDynamicSharedMemorySize, GEMM_DYN);

    // one-time side stream + events
    static cudaStream_t sside = nullptr;
    static cudaEvent_t evFork = nullptr, evW0 = nullptr, evCsr = nullptr, evW12 = nullptr;
    if (!sside) {
        cudaStreamCreateWithFlags(&sside, cudaStreamNonBlocking);
        cudaEventCreateWithFlags(&evFork, cudaEventDisableTiming);
        cudaEventCreateWithFlags(&evW0,   cudaEventDisableTiming);
        cudaEventCreateWithFlags(&evCsr,  cudaEventDisableTiming);
        cudaEventCreateWithFlags(&evW12,  cudaEventDisableTiming);
    }

    // tensor maps
    CUtensorMap mA64h, mA64l, mA512h, mA512l;
    CUtensorMap mB0, mB1, mB2;
    make2d(&mA64h,  dAh, 64, NT);   make2d(&mA64l,  dAl, 64, NT);
    make2d(&mA512h, dAh, 512, NT);  make2d(&mA512l, dAl, 512, NT);
    make2d(&mB0, dBh + WOFF0, 64,  2 * 512);
    make2d(&mB1, dBh + WOFF1, 512, 2 * 512);
    make2d(&mB2, dBh + WOFF2, 512, 2 * 256);

    const int MB = (NT + 127) / 128;   // 79

    // ---- fork side stream immediately ----
    cudaEventRecord(evFork, 0);
    cudaStreamWaitEvent(sside, evFork, 0);

    k_split<<<(NT * 64 + 255) / 256, 256>>>(x, dAh, dAl, NT * 64);                     // main

    k_splitWh<<<dim3((512 * 64 + 255) / 256, 2), 256, 0, sside>>>(Wl[0], Wr[0],
                                                                  dBh + WOFF0, 64, 512);
    cudaEventRecord(evW0, sside);
    cudaMemsetAsync(dDeg, 0, NT * sizeof(int), sside);
    k_hist<<<(NE + 255) / 256, 256, 0, sside>>>(dst);

    // ---------- layer 0 GEMM ----------
    cudaStreamWaitEvent(0, evW0, 0);
    k_gemm_tma<<<dim3(512 / 128, MB, 2), 256, GEMM_DYN>>>(mA64h, mA64l, mB0,
                                                          bl[0], br[0], dXL, dXR, NT, 512, 64);

    k_scan   <<<1, 1024, 0, sside>>>();
    k_scatter<<<(NE + 255) / 256, 256, 0, sside>>>(dst);
    cudaEventRecord(evCsr, sside);
    k_splitWh<<<dim3((512 * 512 + 255) / 256, 2), 256, 0, sside>>>(Wl[1], Wr[1],
                                                                   dBh + WOFF1, 512, 512);
    k_splitWh<<<dim3((256 * 512 + 255) / 256, 2), 256, 0, sside>>>(Wl[2], Wr[2],
                                                                   dBh + WOFF2, 512, 256);
    cudaEventRecord(evW12, sside);

    // ---------- layer 0 aggregate ----------
    cudaStreamWaitEvent(0, evCsr, 0);
    k_gat_agg<4, 128, true, true><<<NT, 128>>>(ew, src, We[0], att[0], bias[0],
                                               nullptr, dAh, dAl);

    // ---------- layer 1 ----------
    cudaStreamWaitEvent(0, evW12, 0);
    k_gemm_tma<<<dim3(512 / 128, MB, 2), 256, GEMM_DYN>>>(mA512h, mA512l, mB1,
                                                          bl[1], br[1], dXL, dXR, NT, 512, 512);
    k_gat_agg<4, 128, true, true><<<NT, 128>>>(ew, src, We[1], att[1], bias[1],
                                               nullptr, dAh, dAl);

    // ---------- layer 2 ----------
    k_gemm_tma<<<dim3(256 / 128, MB, 2), 256, GEMM_DYN>>>(mA512h, mA512l, mB2,
                                                          bl[2], br[2], dXL, dXR, NT, 256, 512);
    k_gat_agg<1, 256, false, false><<<(NT + 3) / 4, 128>>>(ew, src, We[2], att[2], bias[2],
                                                           dOut, nullptr, nullptr);
}